// round 10
// baseline (speedup 1.0000x reference)
#include <cuda_runtime.h>
#include <math.h>
#include <stdint.h>

#define D 128
#define PAD 132            // k_final/k_power smem row pitch (floats)
#define PADG 136           // k_G pitch: mod 32 == 8 -> conflict-free mma fragment loads
#define PADE 129
#define NMAX 65536
#define NSQ 10
#define NREF 5
#define PWB 16             // k_power blocks

static __device__ int   g_degi[NMAX];
static __device__ float g_dinv[NMAX];
static __device__ float g_p[NMAX];
static __device__ float g_sacc[NMAX];
static __device__ float g_scores[NMAX];
static __device__ __align__(16) float g_G[D * D];
static __device__ __align__(16) float g_Ea[D * D];
static __device__ __align__(16) float g_Eb[D * D];
static __device__ float g_v1[D];
static __device__ float g_a1[D];
static __device__ float g_wv[D];
static __device__ float g_bg;
static __device__ int   g_i32;
static __device__ int   g_bar;

// ---------------------------------------------------------------- utilities
__device__ __forceinline__ float sigmoidf_(float z) {
    return 1.0f / (1.0f + expf(-z));
}

__device__ __forceinline__ unsigned smem_u32(const void* p) {
    return (unsigned)__cvta_generic_to_shared(p);
}
__device__ __forceinline__ void cp16(unsigned s, const void* g) {
    asm volatile("cp.async.cg.shared.global [%0], [%1], 16;\n" :: "r"(s), "l"(g));
}
#define CP_COMMIT() asm volatile("cp.async.commit_group;\n" ::)
#define CP_WAIT(n)  asm volatile("cp.async.wait_group %0;\n" :: "n"(n))

__device__ __forceinline__ uint32_t tf32cvt(float f) {
    uint32_t u;
    asm("cvt.rna.tf32.f32 %0, %1;" : "=r"(u) : "f"(f));
    return u;
}

__device__ __forceinline__ void mma_tf32(float* c, uint32_t a0, uint32_t a1, uint32_t a2, uint32_t a3,
                                         uint32_t b0, uint32_t b1) {
    asm volatile("mma.sync.aligned.m16n8k8.row.col.f32.tf32.tf32.f32 "
                 "{%0,%1,%2,%3}, {%4,%5,%6,%7}, {%8,%9}, {%0,%1,%2,%3};"
                 : "+f"(c[0]), "+f"(c[1]), "+f"(c[2]), "+f"(c[3])
                 : "r"(a0), "r"(a1), "r"(a2), "r"(a3), "r"(b0), "r"(b1));
}

// L2-coherent float4 load for cross-block exchange in k_power.
__device__ __forceinline__ float4 ldcg4(const float4* p) {
    float4 v;
    asm volatile("ld.global.cg.v4.f32 {%0,%1,%2,%3}, [%4];"
                 : "=f"(v.x), "=f"(v.y), "=f"(v.z), "=f"(v.w) : "l"(p));
    return v;
}

// ---------------------------------------------------------------- fused prologue (R6: kernel-based zeroing)
__global__ void k_pre(const long long* ei, int E, int N,
                      const float* __restrict__ wg, const float* __restrict__ bgc,
                      const float* __restrict__ ws, const float* __restrict__ bs, int ZB) {
    int b = blockIdx.x, t = threadIdx.x;
    if (b < ZB) {
        int i = b * 256 + t;
        if (i < N) g_degi[i] = 0;
        if (i < D * D) g_G[i] = 0.0f;
        if (i == 0 && b == 0) g_bar = 0;
    } else if (b == ZB) {
        __shared__ int flag;
        if (t == 0) flag = 0;
        __syncthreads();
        int n = E < 1024 ? E : 1024;
        for (int e = t; e < n; e += 256)
            if ((unsigned long long)ei[e] >= (unsigned long long)N) flag = 1;
        __syncthreads();
        if (t == 0) g_i32 = flag;
    } else {
        __shared__ float wss[D];
        if (t < D) wss[t] = ws[t];
        __syncthreads();
        if (t < D) {
            float s = 0.0f;
            #pragma unroll 8
            for (int m = 0; m < D; m++) s += wg[t * D + m] * wss[m];
            g_wv[t] = s;
        }
        if (t == 0) {
            float bsum = bs[0];
            for (int m = 0; m < D; m++) bsum += bgc[m] * wss[m];
            g_bg = bsum;
        }
    }
}

// ---------------------------------------------------------------- edge/score chain (s1)
__global__ void k_p(const float* __restrict__ x, int N) {
    int w = (blockIdx.x * blockDim.x + threadIdx.x) >> 5;
    int lane = threadIdx.x & 31;
    if (w >= N) return;
    float4 xv = ((const float4*)x)[(size_t)w * 32 + lane];
    float4 wv = *(const float4*)&g_wv[lane * 4];
    float s = xv.x * wv.x + xv.y * wv.y + xv.z * wv.z + xv.w * wv.w;
    #pragma unroll
    for (int o = 16; o; o >>= 1) s += __shfl_xor_sync(0xffffffffu, s, o);
    if (lane == 0) g_p[w] = s;
}

__global__ void k_deg(const void* ei, int E) {
    int e = (blockIdx.x * 256 + threadIdx.x) * 2;
    if (e >= E) return;
    if (g_i32) {
        const int* dst = (const int*)ei + E;
        atomicAdd(&g_degi[dst[e]], 1);
        if (e + 1 < E) atomicAdd(&g_degi[dst[e + 1]], 1);
    } else {
        const long long* dst = (const long long*)ei + E;
        if (e + 1 < E) {
            longlong2 d = *(const longlong2*)&dst[e];
            atomicAdd(&g_degi[(int)d.x], 1);
            atomicAdd(&g_degi[(int)d.y], 1);
        } else {
            atomicAdd(&g_degi[(int)dst[e]], 1);
        }
    }
}

__global__ void k_dinv(int N) {
    int i = blockIdx.x * 256 + threadIdx.x;
    if (i >= N) return;
    float di = rsqrtf((float)(g_degi[i] + 1));
    g_dinv[i] = di;
    g_sacc[i] = di * di * g_p[i];
}

__global__ void k_edge(const void* ei, int E) {
    int e = (blockIdx.x * 256 + threadIdx.x) * 2;
    if (e >= E) return;
    if (g_i32) {
        const int* src = (const int*)ei;
        const int* dst = src + E;
        #pragma unroll
        for (int u = 0; u < 2; u++) {
            if (e + u >= E) break;
            int s = src[e + u], t = dst[e + u];
            atomicAdd(&g_sacc[t], g_dinv[s] * g_dinv[t] * g_p[s]);
        }
    } else {
        const long long* src = (const long long*)ei;
        const long long* dst = src + E;
        if (e + 1 < E) {
            longlong2 sv = *(const longlong2*)&src[e];
            longlong2 dv = *(const longlong2*)&dst[e];
            int s0 = (int)sv.x, t0 = (int)dv.x, s1 = (int)sv.y, t1 = (int)dv.y;
            atomicAdd(&g_sacc[t0], g_dinv[s0] * g_dinv[t0] * g_p[s0]);
            atomicAdd(&g_sacc[t1], g_dinv[s1] * g_dinv[t1] * g_p[s1]);
        } else {
            int s = (int)src[e], t = (int)dst[e];
            atomicAdd(&g_sacc[t], g_dinv[s] * g_dinv[t] * g_p[s]);
        }
    }
}

__global__ void k_scores(int N) {
    int i = blockIdx.x * 256 + threadIdx.x;
    if (i >= N) return;
    g_scores[i] = sigmoidf_(g_sacc[i] + g_bg);
}

__global__ void k_gate(const void* ei, const float* __restrict__ ew,
                       const float* __restrict__ al, const float* __restrict__ be,
                       float* __restrict__ out, int E) {
    int e = (blockIdx.x * 256 + threadIdx.x) * 2;
    if (e >= E) return;
    float a_ = al[0], b_ = be[0];
    if (g_i32) {
        const int* src = (const int*)ei;
        const int* dst = src + E;
        #pragma unroll
        for (int u = 0; u < 2; u++) {
            if (e + u >= E) break;
            int s = src[e + u], t = dst[e + u];
            float z = a_ * (g_scores[s] + g_scores[t]) + b_;
            out[e + u] = ew[e + u] * sigmoidf_(z);
        }
    } else {
        const long long* src = (const long long*)ei;
        const long long* dst = src + E;
        if (e + 1 < E) {
            longlong2 sv = *(const longlong2*)&src[e];
            longlong2 dv = *(const longlong2*)&dst[e];
            float2 w = *(const float2*)&ew[e];
            float z0 = a_ * (g_scores[(int)sv.x] + g_scores[(int)dv.x]) + b_;
            float z1 = a_ * (g_scores[(int)sv.y] + g_scores[(int)dv.y]) + b_;
            float2 o = make_float2(w.x * sigmoidf_(z0), w.y * sigmoidf_(z1));
            *(float2*)&out[e] = o;
        } else {
            int s = (int)src[e], t = (int)dst[e];
            float z = a_ * (g_scores[s] + g_scores[t]) + b_;
            out[e] = ew[e] * sigmoidf_(z);
        }
    }
}

// ---------------------------------------------------------------- Gram: tf32 mma, 3-pass hi/lo split (R6)
__global__ __launch_bounds__(512, 1) void k_G(const float* __restrict__ x, int N, int nChunks) {
    extern __shared__ float sm[];
    float* bufs[2] = { sm, sm + 128 * PADG };
    int tid = threadIdx.x;
    int wid = tid >> 5, lane = tid & 31;
    int wm = wid >> 2, wn = wid & 3;
    int gid = lane >> 2, tg = lane & 3;
    int m0 = wm * 32, n0 = wn * 32;
    int stride = gridDim.x;

    float acc[2][4][4];
    #pragma unroll
    for (int mi = 0; mi < 2; mi++)
        #pragma unroll
        for (int ni = 0; ni < 4; ni++)
            #pragma unroll
            for (int j = 0; j < 4; j++) acc[mi][ni][j] = 0.0f;

    int ch = blockIdx.x;
    if (ch < nChunks) {
        int R0 = ch * 128;
        if (R0 + 128 <= N) {
            #pragma unroll
            for (int u = 0; u < 8; u++) {
                int idx = tid + u * 512;
                int r = idx >> 5, c4 = idx & 31;
                cp16(smem_u32(&bufs[0][r * PADG + c4 * 4]), &x[((size_t)(R0 + r)) * 128 + c4 * 4]);
            }
        } else {
            #pragma unroll
            for (int u = 0; u < 8; u++) {
                int idx = tid + u * 512;
                int r = idx >> 5, c4 = idx & 31;
                int gr = R0 + r;
                float4 v = (gr < N) ? ((const float4*)x)[(size_t)gr * 32 + c4]
                                    : make_float4(0.f, 0.f, 0.f, 0.f);
                *(float4*)&bufs[0][r * PADG + c4 * 4] = v;
            }
        }
        CP_COMMIT();
    }

    int cur = 0;
    for (; ch < nChunks; ch += stride) {
        int nxt = ch + stride;
        if (nxt < nChunks) {
            float* bn = bufs[cur ^ 1];
            int R1 = nxt * 128;
            if (R1 + 128 <= N) {
                #pragma unroll
                for (int u = 0; u < 8; u++) {
                    int idx = tid + u * 512;
                    int r = idx >> 5, c4 = idx & 31;
                    cp16(smem_u32(&bn[r * PADG + c4 * 4]), &x[((size_t)(R1 + r)) * 128 + c4 * 4]);
                }
            } else {
                #pragma unroll
                for (int u = 0; u < 8; u++) {
                    int idx = tid + u * 512;
                    int r = idx >> 5, c4 = idx & 31;
                    int gr = R1 + r;
                    float4 v = (gr < N) ? ((const float4*)x)[(size_t)gr * 32 + c4]
                                        : make_float4(0.f, 0.f, 0.f, 0.f);
                    *(float4*)&bn[r * PADG + c4 * 4] = v;
                }
            }
            CP_COMMIT();
            CP_WAIT(1);
        } else {
            CP_WAIT(0);
        }
        __syncthreads();
        const float* bc = bufs[cur];

        #pragma unroll 2
        for (int ks = 0; ks < 16; ks++) {
            int k0 = ks * 8;
            uint32_t ah[2][4], al[2][4];
            #pragma unroll
            for (int mi = 0; mi < 2; mi++) {
                int i0 = m0 + mi * 16 + gid;
                float f0 = bc[(k0 + tg) * PADG + i0];
                float f1 = bc[(k0 + tg) * PADG + i0 + 8];
                float f2 = bc[(k0 + tg + 4) * PADG + i0];
                float f3 = bc[(k0 + tg + 4) * PADG + i0 + 8];
                ah[mi][0] = tf32cvt(f0); al[mi][0] = tf32cvt(f0 - __uint_as_float(ah[mi][0]));
                ah[mi][1] = tf32cvt(f1); al[mi][1] = tf32cvt(f1 - __uint_as_float(ah[mi][1]));
                ah[mi][2] = tf32cvt(f2); al[mi][2] = tf32cvt(f2 - __uint_as_float(ah[mi][2]));
                ah[mi][3] = tf32cvt(f3); al[mi][3] = tf32cvt(f3 - __uint_as_float(ah[mi][3]));
            }
            uint32_t bh[4][2], bl[4][2];
            #pragma unroll
            for (int ni = 0; ni < 4; ni++) {
                int j0 = n0 + ni * 8 + gid;
                float g0 = bc[(k0 + tg) * PADG + j0];
                float g1 = bc[(k0 + tg + 4) * PADG + j0];
                bh[ni][0] = tf32cvt(g0); bl[ni][0] = tf32cvt(g0 - __uint_as_float(bh[ni][0]));
                bh[ni][1] = tf32cvt(g1); bl[ni][1] = tf32cvt(g1 - __uint_as_float(bh[ni][1]));
            }
            #pragma unroll
            for (int mi = 0; mi < 2; mi++)
                #pragma unroll
                for (int ni = 0; ni < 4; ni++) {
                    mma_tf32(acc[mi][ni], ah[mi][0], ah[mi][1], ah[mi][2], ah[mi][3], bh[ni][0], bh[ni][1]);
                    mma_tf32(acc[mi][ni], ah[mi][0], ah[mi][1], ah[mi][2], ah[mi][3], bl[ni][0], bl[ni][1]);
                    mma_tf32(acc[mi][ni], al[mi][0], al[mi][1], al[mi][2], al[mi][3], bh[ni][0], bh[ni][1]);
                }
        }
        cur ^= 1;
        __syncthreads();
    }
    #pragma unroll
    for (int mi = 0; mi < 2; mi++)
        #pragma unroll
        for (int ni = 0; ni < 4; ni++) {
            int r = m0 + mi * 16 + gid, c = n0 + ni * 8 + 2 * tg;
            atomicAdd(&g_G[r * D + c],           acc[mi][ni][0]);
            atomicAdd(&g_G[r * D + c + 1],       acc[mi][ni][1]);
            atomicAdd(&g_G[(r + 8) * D + c],     acc[mi][ni][2]);
            atomicAdd(&g_G[(r + 8) * D + c + 1], acc[mi][ni][3]);
        }
}

// ---------------------------------------------------------------- fused power iteration + extract (R6 + hardening)
__global__ __launch_bounds__(1024, 1) void k_power(const float* __restrict__ w1) {
    extern __shared__ float sm[];
    float* As = sm;
    int tid = threadIdx.x;
    int ty = tid >> 7;
    int tx = tid & 127;
    int wid = tid >> 5, lane = tid & 31;
    int r = blockIdx.x * 8 + ty;
    __shared__ float redm[32];

    for (int it = 0; it < NSQ; it++) {
        const float* in = (it == 0) ? g_G : ((it & 1) ? g_Ea : g_Eb);
        float* outp = (it & 1) ? g_Eb : g_Ea;
        float m = 0.0f;
        #pragma unroll
        for (int u = 0; u < 4; u++) {
            int idx = tid + u * 1024;
            int rr = idx >> 5, c4 = idx & 31;
            float4 v = ldcg4(&((const float4*)in)[idx]);
            *(float4*)&As[rr * PAD + c4 * 4] = v;
            m = fmaxf(m, fmaxf(fmaxf(fabsf(v.x), fabsf(v.y)), fmaxf(fabsf(v.z), fabsf(v.w))));
        }
        #pragma unroll
        for (int o = 16; o; o >>= 1) m = fmaxf(m, __shfl_xor_sync(0xffffffffu, m, o));
        if (lane == 0) redm[wid] = m;
        __syncthreads();
        if (tid < 32) {
            float mm = redm[tid];
            #pragma unroll
            for (int o = 16; o; o >>= 1) mm = fmaxf(mm, __shfl_xor_sync(0xffffffffu, mm, o));
            if (tid == 0) redm[0] = mm;
        }
        __syncthreads();
        float inv = 1.0f / redm[0];
        float inv2 = inv * inv;

        float acc = 0.0f;
        #pragma unroll 8
        for (int k = 0; k < D; k++) acc += As[r * PAD + k] * As[k * PAD + tx];
        outp[r * D + tx] = acc * inv2;

        __threadfence();
        __syncthreads();
        if (tid == 0) {
            atomicAdd(&g_bar, 1);
            int target = PWB * (it + 1);
            while (*(volatile int*)&g_bar < target) { __nanosleep(64); }
            __threadfence();
        }
        __syncthreads();
    }

    if (blockIdx.x != 0) return;

    float* vv = sm + D * PADE;
    float* uu = vv + D;
    float* red = uu + D;
    __shared__ int redi[128];
    __shared__ int jm;
    const float* P = (NSQ & 1) ? g_Eb : g_Ea;
    for (int idx4 = tid; idx4 < D * D / 4; idx4 += 1024) {
        float4 v = ldcg4(&((const float4*)P)[idx4]);
        int idx = idx4 * 4;
        int rr = idx >> 7, c = idx & 127;
        As[rr * PADE + c + 0] = v.x;
        As[rr * PADE + c + 1] = v.y;
        As[rr * PADE + c + 2] = v.z;
        As[rr * PADE + c + 3] = v.w;
    }
    __syncthreads();
    if (tid < D) { red[tid] = As[tid * PADE + tid]; redi[tid] = tid; }
    __syncthreads();
    for (int s = 64; s > 0; s >>= 1) {
        if (tid < s && red[tid + s] > red[tid]) { red[tid] = red[tid + s]; redi[tid] = redi[tid + s]; }
        __syncthreads();
    }
    if (tid == 0) jm = redi[0];
    __syncthreads();
    if (tid < D) vv[tid] = As[jm * PADE + tid];
    __syncthreads();

    for (int itr = 0; itr < NREF; itr++) {
        if (tid < D) {
            float s = 0.0f;
            #pragma unroll 8
            for (int c = 0; c < D; c++) s += As[tid * PADE + c] * vv[c];
            uu[tid] = s;
            red[tid] = s * s;
        }
        __syncthreads();
        for (int r2 = 64; r2 > 0; r2 >>= 1) {
            if (tid < r2) red[tid] += red[tid + r2];
            __syncthreads();
        }
        float invn = rsqrtf(fmaxf(red[0], 1e-30f));
        __syncthreads();
        if (tid < D) vv[tid] = uu[tid] * invn;
        __syncthreads();
    }

    if (tid < D) {
        g_v1[tid] = vv[tid];
        float a = 0.0f;
        #pragma unroll 8
        for (int d2 = 0; d2 < D; d2++) a += vv[d2] * w1[d2 * D + tid];
        g_a1[tid] = a;
    }
}

// ---------------------------------------------------------------- fused enhancer, tf32 mma (R6: q over 128 threads)
__global__ __launch_bounds__(512, 1) void k_final3(const float* __restrict__ x,
                        const float* __restrict__ b1, const float* __restrict__ b2,
                        const float* __restrict__ w1, const float* __restrict__ w2,
                        float* __restrict__ out, int N, int nChunks) {
    extern __shared__ float sm[];
    float* xs  = sm;
    float* w1t = sm + 128 * PAD;
    float* w2t = w1t + 128 * PAD;
    float* q_s = w2t + 128 * PAD;
    float* sc_s = q_s + 128;
    __shared__ float v1_s[D], a1_s[D], be1_s[D], be2_s[D];

    int tid = threadIdx.x;
    int wid = tid >> 5, lane = tid & 31;
    int wm = wid >> 2, wn = wid & 3;
    int gid = lane >> 2, tg = lane & 3;
    int stride = gridDim.x;

    for (int idx = tid; idx < D * D; idx += 512) {
        int k = idx >> 7, n = idx & 127;
        w1t[n * PAD + k] = __uint_as_float(tf32cvt(w1[idx]));
        w2t[n * PAD + k] = __uint_as_float(tf32cvt(w2[idx]));
    }
    if (tid < D) {
        v1_s[tid] = g_v1[tid]; a1_s[tid] = g_a1[tid];
        be1_s[tid] = b1[tid];  be2_s[tid] = b2[tid];
    }

    float4 pf[8];
    int ch = blockIdx.x;
    if (ch < nChunks) {
        int R0 = ch * 128;
        #pragma unroll
        for (int u = 0; u < 8; u++) {
            int idx = tid + u * 512;
            int r = idx >> 5, c4 = idx & 31;
            int gr = R0 + r;
            pf[u] = (gr < N) ? ((const float4*)x)[(size_t)gr * 32 + c4]
                             : make_float4(0.f, 0.f, 0.f, 0.f);
        }
    }

    for (; ch < nChunks; ch += stride) {
        int R0 = ch * 128;
        __syncthreads();
        #pragma unroll
        for (int u = 0; u < 8; u++) {
            int idx = tid + u * 512;
            int r = idx >> 5, c4 = idx & 31;
            *(float4*)&xs[r * PAD + c4 * 4] = pf[u];
        }
        if (tid < 128) sc_s[tid] = (R0 + tid < N) ? g_scores[R0 + tid] : 0.0f;
        __syncthreads();
        if (tid < 128) {
            float q = 0.0f;
            #pragma unroll 8
            for (int d = 0; d < D; d++) q += xs[tid * PAD + d] * v1_s[d];
            q_s[tid] = q;
        }
        int nxt = ch + stride;
        if (nxt < nChunks) {
            int R1 = nxt * 128;
            #pragma unroll
            for (int u = 0; u < 8; u++) {
                int idx = tid + u * 512;
                int r = idx >> 5, c4 = idx & 31;
                int gr = R1 + r;
                pf[u] = (gr < N) ? ((const float4*)x)[(size_t)gr * 32 + c4]
                                 : make_float4(0.f, 0.f, 0.f, 0.f);
            }
        }
        __syncthreads();

        // GEMM1: z = x @ W1 (A hi/lo split)
        float cfr[2][4][4];
        #pragma unroll
        for (int mi = 0; mi < 2; mi++)
            #pragma unroll
            for (int ni = 0; ni < 4; ni++)
                #pragma unroll
                for (int j = 0; j < 4; j++) cfr[mi][ni][j] = 0.0f;

        #pragma unroll 2
        for (int ks = 0; ks < 16; ks++) {
            int k0 = ks * 8;
            uint32_t ah[2][4], al[2][4];
            #pragma unroll
            for (int mi = 0; mi < 2; mi++) {
                int r = wm * 32 + mi * 16 + gid;
                float f0 = xs[r * PAD + k0 + tg];
                float f1 = xs[(r + 8) * PAD + k0 + tg];
                float f2 = xs[r * PAD + k0 + tg + 4];
                float f3 = xs[(r + 8) * PAD + k0 + tg + 4];
                ah[mi][0] = tf32cvt(f0); al[mi][0] = tf32cvt(f0 - __uint_as_float(ah[mi][0]));
                ah[mi][1] = tf32cvt(f1); al[mi][1] = tf32cvt(f1 - __uint_as_float(ah[mi][1]));
                ah[mi][2] = tf32cvt(f2); al[mi][2] = tf32cvt(f2 - __uint_as_float(ah[mi][2]));
                ah[mi][3] = tf32cvt(f3); al[mi][3] = tf32cvt(f3 - __uint_as_float(ah[mi][3]));
            }
            uint32_t bh[4][2];
            #pragma unroll
            for (int ni = 0; ni < 4; ni++) {
                int c = wn * 32 + ni * 8 + gid;
                bh[ni][0] = __float_as_uint(w1t[c * PAD + k0 + tg]);
                bh[ni][1] = __float_as_uint(w1t[c * PAD + k0 + tg + 4]);
            }
            #pragma unroll
            for (int mi = 0; mi < 2; mi++)
                #pragma unroll
                for (int ni = 0; ni < 4; ni++) {
                    mma_tf32(cfr[mi][ni], ah[mi][0], ah[mi][1], ah[mi][2], ah[mi][3], bh[ni][0], bh[ni][1]);
                    mma_tf32(cfr[mi][ni], al[mi][0], al[mi][1], al[mi][2], al[mi][3], bh[ni][0], bh[ni][1]);
                }
        }
        __syncthreads();

        // epilogue1: relu(0.5*acc + 0.5*q*a1 + b1), store PRE-ROUNDED tf32
        #pragma unroll
        for (int mi = 0; mi < 2; mi++) {
            int r = wm * 32 + mi * 16 + gid;
            float qh0 = 0.5f * q_s[r], qh8 = 0.5f * q_s[r + 8];
            #pragma unroll
            for (int ni = 0; ni < 4; ni++) {
                int c = wn * 32 + ni * 8 + 2 * tg;
                float z00 = 0.5f * cfr[mi][ni][0] + qh0 * a1_s[c]     + be1_s[c];
                float z01 = 0.5f * cfr[mi][ni][1] + qh0 * a1_s[c + 1] + be1_s[c + 1];
                float z10 = 0.5f * cfr[mi][ni][2] + qh8 * a1_s[c]     + be1_s[c];
                float z11 = 0.5f * cfr[mi][ni][3] + qh8 * a1_s[c + 1] + be1_s[c + 1];
                float2 p0 = make_float2(__uint_as_float(tf32cvt(fmaxf(z00, 0.f))),
                                        __uint_as_float(tf32cvt(fmaxf(z01, 0.f))));
                float2 p1 = make_float2(__uint_as_float(tf32cvt(fmaxf(z10, 0.f))),
                                        __uint_as_float(tf32cvt(fmaxf(z11, 0.f))));
                *(float2*)&xs[r * PAD + c]       = p0;
                *(float2*)&xs[(r + 8) * PAD + c] = p1;
            }
        }
        __syncthreads();

        // GEMM2: single pass, A pre-rounded
        #pragma unroll
        for (int mi = 0; mi < 2; mi++)
            #pragma unroll
            for (int ni = 0; ni < 4; ni++)
                #pragma unroll
                for (int j = 0; j < 4; j++) cfr[mi][ni][j] = 0.0f;

        #pragma unroll 2
        for (int ks = 0; ks < 16; ks++) {
            int k0 = ks * 8;
            uint32_t a2[2][4];
            #pragma unroll
            for (int mi = 0; mi < 2; mi++) {
                int r = wm * 32 + mi * 16 + gid;
                a2[mi][0] = __float_as_uint(xs[r * PAD + k0 + tg]);
                a2[mi][1] = __float_as_uint(xs[(r + 8) * PAD + k0 + tg]);
                a2[mi][2] = __float_as_uint(xs[r * PAD + k0 + tg + 4]);
                a2[mi][3] = __float_as_uint(xs[(r + 8) * PAD + k0 + tg + 4]);
            }
            uint32_t bh[4][2];
            #pragma unroll
            for (int ni = 0; ni < 4; ni++) {
                int c = wn * 32 + ni * 8 + gid;
                bh[ni][0] = __float_as_uint(w2t[c * PAD + k0 + tg]);
                bh[ni][1] = __float_as_uint(w2t[c * PAD + k0 + tg + 4]);
            }
            #pragma unroll
            for (int mi = 0; mi < 2; mi++)
                #pragma unroll
                for (int ni = 0; ni < 4; ni++)
                    mma_tf32(cfr[mi][ni], a2[mi][0], a2[mi][1], a2[mi][2], a2[mi][3], bh[ni][0], bh[ni][1]);
        }

        // epilogue2
        #pragma unroll
        for (int mi = 0; mi < 2; mi++) {
            int r = wm * 32 + mi * 16 + gid;
            #pragma unroll
            for (int rr = 0; rr < 2; rr++) {
                int row = r + rr * 8;
                int gr = R0 + row;
                if (gr >= N) continue;
                float sc = sc_s[row], qh = 0.5f * q_s[row];
                #pragma unroll
                for (int ni = 0; ni < 4; ni++) {
                    int c = wn * 32 + ni * 8 + 2 * tg;
                    float e0 = cfr[mi][ni][rr * 2 + 0];
                    float e1 = cfr[mi][ni][rr * 2 + 1];
                    float2 xv = ((const float2*)x)[(size_t)gr * 64 + (c >> 1)];
                    float o0 = (e0 + be2_s[c])     * sc + 0.5f * xv.x + qh * v1_s[c];
                    float o1 = (e1 + be2_s[c + 1]) * sc + 0.5f * xv.y + qh * v1_s[c + 1];
                    ((float2*)out)[(size_t)gr * 64 + (c >> 1)] = make_float2(o0, o1);
                }
            }
        }
    }
}

// ---------------------------------------------------------------- launch (R6 schedule)
extern "C" void kernel_launch(void* const* d_in, const int* in_sizes, int n_in,
                              void* d_out, int out_size) {
    const float* x       = (const float*)d_in[0];
    const void*  ei      = d_in[1];
    const float* ew      = (const float*)d_in[2];
    const float* w_gcn   = (const float*)d_in[3];
    const float* b_gcn   = (const float*)d_in[4];
    const float* w_score = (const float*)d_in[5];
    const float* b_score = (const float*)d_in[6];
    const float* alpha   = (const float*)d_in[7];
    const float* beta    = (const float*)d_in[8];
    const float* w_e1    = (const float*)d_in[9];
    const float* b_e1    = (const float*)d_in[10];
    const float* w_e2    = (const float*)d_in[11];
    const float* b_e2    = (const float*)d_in[12];
    float* out = (float*)d_out;

    int N = in_sizes[0] / D;
    int E = in_sizes[2];
    int nChunks = (N + 127) / 128;
    int NB = (N + 255) / 256;
    int E2 = (E + 1) / 2;
    int EB2 = (E2 + 255) / 256;
    int ZB = ((N > D * D ? N : D * D) + 255) / 256;
    int PB = (N * 32 + 255) / 256;

    const int SMG = 2 * 128 * PADG * 4;
    const int SMF = (3 * 128 * PAD + 256) * 4;
    const int SMP = (128 * PAD) * 4;

    static int init_done = 0;
    static cudaStream_t s1;
    static cudaEvent_t evFork, evJoin;
    if (!init_done) {
        cudaFuncSetAttribute(k_G,      cudaFuncAttributeMaxDynamicSharedMemorySize, SMG);
        cudaFuncSetAttribute(k_power,  cudaFuncAttributeMaxDynamicSharedMemorySize, SMP);
        cudaFuncSetAttribute(k_final3, cudaFuncAttributeMaxDynamicSharedMemorySize, SMF);
        cudaStreamCreateWithFlags(&s1, cudaStreamNonBlocking);
        cudaEventCreateWithFlags(&evFork, cudaEventDisableTiming);
        cudaEventCreateWithFlags(&evJoin, cudaEventDisableTiming);
        init_done = 1;
    }

    k_pre<<<ZB + 2, 256>>>((const long long*)ei, E, N, w_gcn, b_gcn, w_score, b_score, ZB);

    cudaEventRecord(evFork, 0);
    cudaStreamWaitEvent(s1, evFork, 0);

    k_deg<<<EB2, 256, 0, s1>>>(ei, E);
    k_p<<<PB, 256, 0, s1>>>(x, N);
    k_dinv<<<NB, 256, 0, s1>>>(N);
    k_edge<<<EB2, 256, 0, s1>>>(ei, E);
    k_scores<<<NB, 256, 0, s1>>>(N);
    k_gate<<<EB2, 256, 0, s1>>>(ei, ew, alpha, beta, out + (size_t)N * D, E);
    cudaEventRecord(evJoin, s1);

    k_G<<<148, 512, SMG>>>(x, N, nChunks);
    k_power<<<PWB, 1024, SMP>>>(w_e1);

    cudaStreamWaitEvent(0, evJoin, 0);
    k_final3<<<148, 512, SMF>>>(x, b_e1, b_e2, w_e1, w_e2, out, N, nChunks);
}

// round 11
// speedup vs baseline: 1.0521x; 1.0521x over previous
#include <cuda_runtime.h>
#include <math.h>
#include <stdint.h>

#define D 128
#define PAD 132            // k_final/k_power smem row pitch (floats)
#define PADG 136           // k_G pitch: mod 32 == 8 -> conflict-free mma fragment loads
#define PADE 129
#define NMAX 65536
#define NSQ 10
#define NREF 5
#define PWB 16             // k_power blocks

static __device__ int   g_degi[NMAX];
static __device__ float g_dinv[NMAX];
static __device__ float g_p[NMAX];
static __device__ float g_sacc[NMAX];
static __device__ float g_scores[NMAX];
static __device__ __align__(16) float g_G[D * D];
static __device__ __align__(16) float g_Ea[D * D];
static __device__ __align__(16) float g_Eb[D * D];
static __device__ float g_v1[D];
static __device__ float g_a1[D];
static __device__ float g_wv[D];
static __device__ float g_bg;
static __device__ int   g_i32;
static __device__ int   g_bar;

// ---------------------------------------------------------------- utilities
__device__ __forceinline__ float sigmoidf_(float z) {
    return 1.0f / (1.0f + expf(-z));
}

__device__ __forceinline__ unsigned smem_u32(const void* p) {
    return (unsigned)__cvta_generic_to_shared(p);
}
__device__ __forceinline__ void cp16(unsigned s, const void* g) {
    asm volatile("cp.async.cg.shared.global [%0], [%1], 16;\n" :: "r"(s), "l"(g));
}
#define CP_COMMIT() asm volatile("cp.async.commit_group;\n" ::)
#define CP_WAIT(n)  asm volatile("cp.async.wait_group %0;\n" :: "n"(n))

__device__ __forceinline__ uint32_t tf32cvt(float f) {
    uint32_t u;
    asm("cvt.rna.tf32.f32 %0, %1;" : "=r"(u) : "f"(f));
    return u;
}

__device__ __forceinline__ void mma_tf32(float* c, uint32_t a0, uint32_t a1, uint32_t a2, uint32_t a3,
                                         uint32_t b0, uint32_t b1) {
    asm volatile("mma.sync.aligned.m16n8k8.row.col.f32.tf32.tf32.f32 "
                 "{%0,%1,%2,%3}, {%4,%5,%6,%7}, {%8,%9}, {%0,%1,%2,%3};"
                 : "+f"(c[0]), "+f"(c[1]), "+f"(c[2]), "+f"(c[3])
                 : "r"(a0), "r"(a1), "r"(a2), "r"(a3), "r"(b0), "r"(b1));
}

// L2-coherent float4 load for cross-block exchange in k_power.
__device__ __forceinline__ float4 ldcg4(const float4* p) {
    float4 v;
    asm volatile("ld.global.cg.v4.f32 {%0,%1,%2,%3}, [%4];"
                 : "=f"(v.x), "=f"(v.y), "=f"(v.z), "=f"(v.w) : "l"(p));
    return v;
}

// ---------------------------------------------------------------- s0 micro-prologue: zero g_G + g_bar
__global__ void k_zeroG() {
    int i = blockIdx.x * 256 + threadIdx.x;     // 16*256 = 4096 = D*D/4
    ((float4*)g_G)[i] = make_float4(0.f, 0.f, 0.f, 0.f);
    if (i == 0) g_bar = 0;
}

// ---------------------------------------------------------------- s1 prologue: zero degi + detect + wv/bg
__global__ void k_pre2(const long long* ei, int E, int N,
                       const float* __restrict__ wg, const float* __restrict__ bgc,
                       const float* __restrict__ ws, const float* __restrict__ bs, int ZB) {
    int b = blockIdx.x, t = threadIdx.x;
    if (b < ZB) {
        int i = b * 256 + t;
        if (i < N) g_degi[i] = 0;
    } else if (b == ZB) {
        __shared__ int flag;
        if (t == 0) flag = 0;
        __syncthreads();
        int n = E < 1024 ? E : 1024;
        for (int e = t; e < n; e += 256)
            if ((unsigned long long)ei[e] >= (unsigned long long)N) flag = 1;
        __syncthreads();
        if (t == 0) g_i32 = flag;
    } else {
        __shared__ float wss[D];
        if (t < D) wss[t] = ws[t];
        __syncthreads();
        if (t < D) {
            float s = 0.0f;
            #pragma unroll 8
            for (int m = 0; m < D; m++) s += wg[t * D + m] * wss[m];
            g_wv[t] = s;
        }
        if (t == 0) {
            float bsum = bs[0];
            for (int m = 0; m < D; m++) bsum += bgc[m] * wss[m];
            g_bg = bsum;
        }
    }
}

// ---------------------------------------------------------------- edge/score chain (s1)
__global__ void k_p(const float* __restrict__ x, int N) {
    int w = (blockIdx.x * blockDim.x + threadIdx.x) >> 5;
    int lane = threadIdx.x & 31;
    if (w >= N) return;
    float4 xv = ((const float4*)x)[(size_t)w * 32 + lane];
    float4 wv = *(const float4*)&g_wv[lane * 4];
    float s = xv.x * wv.x + xv.y * wv.y + xv.z * wv.z + xv.w * wv.w;
    #pragma unroll
    for (int o = 16; o; o >>= 1) s += __shfl_xor_sync(0xffffffffu, s, o);
    if (lane == 0) g_p[w] = s;
}

__global__ void k_deg(const void* ei, int E) {
    int e = (blockIdx.x * 256 + threadIdx.x) * 2;
    if (e >= E) return;
    if (g_i32) {
        const int* dst = (const int*)ei + E;
        atomicAdd(&g_degi[dst[e]], 1);
        if (e + 1 < E) atomicAdd(&g_degi[dst[e + 1]], 1);
    } else {
        const long long* dst = (const long long*)ei + E;
        if (e + 1 < E) {
            longlong2 d = *(const longlong2*)&dst[e];
            atomicAdd(&g_degi[(int)d.x], 1);
            atomicAdd(&g_degi[(int)d.y], 1);
        } else {
            atomicAdd(&g_degi[(int)dst[e]], 1);
        }
    }
}

__global__ void k_dinv(int N) {
    int i = blockIdx.x * 256 + threadIdx.x;
    if (i >= N) return;
    float di = rsqrtf((float)(g_degi[i] + 1));
    g_dinv[i] = di;
    g_sacc[i] = di * di * g_p[i];
}

__global__ void k_edge(const void* ei, int E) {
    int e = (blockIdx.x * 256 + threadIdx.x) * 2;
    if (e >= E) return;
    if (g_i32) {
        const int* src = (const int*)ei;
        const int* dst = src + E;
        #pragma unroll
        for (int u = 0; u < 2; u++) {
            if (e + u >= E) break;
            int s = src[e + u], t = dst[e + u];
            atomicAdd(&g_sacc[t], g_dinv[s] * g_dinv[t] * g_p[s]);
        }
    } else {
        const long long* src = (const long long*)ei;
        const long long* dst = src + E;
        if (e + 1 < E) {
            longlong2 sv = *(const longlong2*)&src[e];
            longlong2 dv = *(const longlong2*)&dst[e];
            int s0 = (int)sv.x, t0 = (int)dv.x, s1 = (int)sv.y, t1 = (int)dv.y;
            atomicAdd(&g_sacc[t0], g_dinv[s0] * g_dinv[t0] * g_p[s0]);
            atomicAdd(&g_sacc[t1], g_dinv[s1] * g_dinv[t1] * g_p[s1]);
        } else {
            int s = (int)src[e], t = (int)dst[e];
            atomicAdd(&g_sacc[t], g_dinv[s] * g_dinv[t] * g_p[s]);
        }
    }
}

__global__ void k_scores(int N) {
    int i = blockIdx.x * 256 + threadIdx.x;
    if (i >= N) return;
    g_scores[i] = sigmoidf_(g_sacc[i] + g_bg);
}

__global__ void k_gate(const void* ei, const float* __restrict__ ew,
                       const float* __restrict__ al, const float* __restrict__ be,
                       float* __restrict__ out, int E) {
    int e = (blockIdx.x * 256 + threadIdx.x) * 2;
    if (e >= E) return;
    float a_ = al[0], b_ = be[0];
    if (g_i32) {
        const int* src = (const int*)ei;
        const int* dst = src + E;
        #pragma unroll
        for (int u = 0; u < 2; u++) {
            if (e + u >= E) break;
            int s = src[e + u], t = dst[e + u];
            float z = a_ * (g_scores[s] + g_scores[t]) + b_;
            out[e + u] = ew[e + u] * sigmoidf_(z);
        }
    } else {
        const long long* src = (const long long*)ei;
        const long long* dst = src + E;
        if (e + 1 < E) {
            longlong2 sv = *(const longlong2*)&src[e];
            longlong2 dv = *(const longlong2*)&dst[e];
            float2 w = *(const float2*)&ew[e];
            float z0 = a_ * (g_scores[(int)sv.x] + g_scores[(int)dv.x]) + b_;
            float z1 = a_ * (g_scores[(int)sv.y] + g_scores[(int)dv.y]) + b_;
            float2 o = make_float2(w.x * sigmoidf_(z0), w.y * sigmoidf_(z1));
            *(float2*)&out[e] = o;
        } else {
            int s = (int)src[e], t = (int)dst[e];
            float z = a_ * (g_scores[s] + g_scores[t]) + b_;
            out[e] = ew[e] * sigmoidf_(z);
        }
    }
}

// ---------------------------------------------------------------- Gram: tf32 mma, 3-pass hi/lo split
__global__ __launch_bounds__(512, 1) void k_G(const float* __restrict__ x, int N, int nChunks) {
    extern __shared__ float sm[];
    float* bufs[2] = { sm, sm + 128 * PADG };
    int tid = threadIdx.x;
    int wid = tid >> 5, lane = tid & 31;
    int wm = wid >> 2, wn = wid & 3;
    int gid = lane >> 2, tg = lane & 3;
    int m0 = wm * 32, n0 = wn * 32;
    int stride = gridDim.x;

    float acc[2][4][4];
    #pragma unroll
    for (int mi = 0; mi < 2; mi++)
        #pragma unroll
        for (int ni = 0; ni < 4; ni++)
            #pragma unroll
            for (int j = 0; j < 4; j++) acc[mi][ni][j] = 0.0f;

    int ch = blockIdx.x;
    if (ch < nChunks) {
        int R0 = ch * 128;
        if (R0 + 128 <= N) {
            #pragma unroll
            for (int u = 0; u < 8; u++) {
                int idx = tid + u * 512;
                int r = idx >> 5, c4 = idx & 31;
                cp16(smem_u32(&bufs[0][r * PADG + c4 * 4]), &x[((size_t)(R0 + r)) * 128 + c4 * 4]);
            }
        } else {
            #pragma unroll
            for (int u = 0; u < 8; u++) {
                int idx = tid + u * 512;
                int r = idx >> 5, c4 = idx & 31;
                int gr = R0 + r;
                float4 v = (gr < N) ? ((const float4*)x)[(size_t)gr * 32 + c4]
                                    : make_float4(0.f, 0.f, 0.f, 0.f);
                *(float4*)&bufs[0][r * PADG + c4 * 4] = v;
            }
        }
        CP_COMMIT();
    }

    int cur = 0;
    for (; ch < nChunks; ch += stride) {
        int nxt = ch + stride;
        if (nxt < nChunks) {
            float* bn = bufs[cur ^ 1];
            int R1 = nxt * 128;
            if (R1 + 128 <= N) {
                #pragma unroll
                for (int u = 0; u < 8; u++) {
                    int idx = tid + u * 512;
                    int r = idx >> 5, c4 = idx & 31;
                    cp16(smem_u32(&bn[r * PADG + c4 * 4]), &x[((size_t)(R1 + r)) * 128 + c4 * 4]);
                }
            } else {
                #pragma unroll
                for (int u = 0; u < 8; u++) {
                    int idx = tid + u * 512;
                    int r = idx >> 5, c4 = idx & 31;
                    int gr = R1 + r;
                    float4 v = (gr < N) ? ((const float4*)x)[(size_t)gr * 32 + c4]
                                        : make_float4(0.f, 0.f, 0.f, 0.f);
                    *(float4*)&bn[r * PADG + c4 * 4] = v;
                }
            }
            CP_COMMIT();
            CP_WAIT(1);
        } else {
            CP_WAIT(0);
        }
        __syncthreads();
        const float* bc = bufs[cur];

        #pragma unroll 2
        for (int ks = 0; ks < 16; ks++) {
            int k0 = ks * 8;
            uint32_t ah[2][4], al[2][4];
            #pragma unroll
            for (int mi = 0; mi < 2; mi++) {
                int i0 = m0 + mi * 16 + gid;
                float f0 = bc[(k0 + tg) * PADG + i0];
                float f1 = bc[(k0 + tg) * PADG + i0 + 8];
                float f2 = bc[(k0 + tg + 4) * PADG + i0];
                float f3 = bc[(k0 + tg + 4) * PADG + i0 + 8];
                ah[mi][0] = tf32cvt(f0); al[mi][0] = tf32cvt(f0 - __uint_as_float(ah[mi][0]));
                ah[mi][1] = tf32cvt(f1); al[mi][1] = tf32cvt(f1 - __uint_as_float(ah[mi][1]));
                ah[mi][2] = tf32cvt(f2); al[mi][2] = tf32cvt(f2 - __uint_as_float(ah[mi][2]));
                ah[mi][3] = tf32cvt(f3); al[mi][3] = tf32cvt(f3 - __uint_as_float(ah[mi][3]));
            }
            uint32_t bh[4][2], bl[4][2];
            #pragma unroll
            for (int ni = 0; ni < 4; ni++) {
                int j0 = n0 + ni * 8 + gid;
                float g0 = bc[(k0 + tg) * PADG + j0];
                float g1 = bc[(k0 + tg + 4) * PADG + j0];
                bh[ni][0] = tf32cvt(g0); bl[ni][0] = tf32cvt(g0 - __uint_as_float(bh[ni][0]));
                bh[ni][1] = tf32cvt(g1); bl[ni][1] = tf32cvt(g1 - __uint_as_float(bh[ni][1]));
            }
            #pragma unroll
            for (int mi = 0; mi < 2; mi++)
                #pragma unroll
                for (int ni = 0; ni < 4; ni++) {
                    mma_tf32(acc[mi][ni], ah[mi][0], ah[mi][1], ah[mi][2], ah[mi][3], bh[ni][0], bh[ni][1]);
                    mma_tf32(acc[mi][ni], ah[mi][0], ah[mi][1], ah[mi][2], ah[mi][3], bl[ni][0], bl[ni][1]);
                    mma_tf32(acc[mi][ni], al[mi][0], al[mi][1], al[mi][2], al[mi][3], bh[ni][0], bh[ni][1]);
                }
        }
        cur ^= 1;
        __syncthreads();
    }
    #pragma unroll
    for (int mi = 0; mi < 2; mi++)
        #pragma unroll
        for (int ni = 0; ni < 4; ni++) {
            int r = m0 + mi * 16 + gid, c = n0 + ni * 8 + 2 * tg;
            atomicAdd(&g_G[r * D + c],           acc[mi][ni][0]);
            atomicAdd(&g_G[r * D + c + 1],       acc[mi][ni][1]);
            atomicAdd(&g_G[(r + 8) * D + c],     acc[mi][ni][2]);
            atomicAdd(&g_G[(r + 8) * D + c + 1], acc[mi][ni][3]);
        }
}

// ---------------------------------------------------------------- fused power iteration + extract
__global__ __launch_bounds__(1024, 1) void k_power(const float* __restrict__ w1) {
    extern __shared__ float sm[];
    float* As = sm;
    int tid = threadIdx.x;
    int ty = tid >> 7;
    int tx = tid & 127;
    int wid = tid >> 5, lane = tid & 31;
    int r = blockIdx.x * 8 + ty;
    __shared__ float redm[32];

    for (int it = 0; it < NSQ; it++) {
        const float* in = (it == 0) ? g_G : ((it & 1) ? g_Ea : g_Eb);
        float* outp = (it & 1) ? g_Eb : g_Ea;
        float m = 0.0f;
        #pragma unroll
        for (int u = 0; u < 4; u++) {
            int idx = tid + u * 1024;
            int rr = idx >> 5, c4 = idx & 31;
            float4 v = ldcg4(&((const float4*)in)[idx]);
            *(float4*)&As[rr * PAD + c4 * 4] = v;
            m = fmaxf(m, fmaxf(fmaxf(fabsf(v.x), fabsf(v.y)), fmaxf(fabsf(v.z), fabsf(v.w))));
        }
        #pragma unroll
        for (int o = 16; o; o >>= 1) m = fmaxf(m, __shfl_xor_sync(0xffffffffu, m, o));
        if (lane == 0) redm[wid] = m;
        __syncthreads();
        if (tid < 32) {
            float mm = redm[tid];
            #pragma unroll
            for (int o = 16; o; o >>= 1) mm = fmaxf(mm, __shfl_xor_sync(0xffffffffu, mm, o));
            if (tid == 0) redm[0] = mm;
        }
        __syncthreads();
        float inv = 1.0f / redm[0];
        float inv2 = inv * inv;

        float acc = 0.0f;
        #pragma unroll 8
        for (int k = 0; k < D; k++) acc += As[r * PAD + k] * As[k * PAD + tx];
        outp[r * D + tx] = acc * inv2;

        __threadfence();
        __syncthreads();
        if (tid == 0) {
            atomicAdd(&g_bar, 1);
            int target = PWB * (it + 1);
            while (*(volatile int*)&g_bar < target) { __nanosleep(64); }
            __threadfence();
        }
        __syncthreads();
    }

    if (blockIdx.x != 0) return;

    float* vv = sm + D * PADE;
    float* uu = vv + D;
    float* red = uu + D;
    __shared__ int redi[128];
    __shared__ int jm;
    const float* P = (NSQ & 1) ? g_Eb : g_Ea;
    for (int idx4 = tid; idx4 < D * D / 4; idx4 += 1024) {
        float4 v = ldcg4(&((const float4*)P)[idx4]);
        int idx = idx4 * 4;
        int rr = idx >> 7, c = idx & 127;
        As[rr * PADE + c + 0] = v.x;
        As[rr * PADE + c + 1] = v.y;
        As[rr * PADE + c + 2] = v.z;
        As[rr * PADE + c + 3] = v.w;
    }
    __syncthreads();
    if (tid < D) { red[tid] = As[tid * PADE + tid]; redi[tid] = tid; }
    __syncthreads();
    for (int s = 64; s > 0; s >>= 1) {
        if (tid < s && red[tid + s] > red[tid]) { red[tid] = red[tid + s]; redi[tid] = redi[tid + s]; }
        __syncthreads();
    }
    if (tid == 0) jm = redi[0];
    __syncthreads();
    if (tid < D) vv[tid] = As[jm * PADE + tid];
    __syncthreads();

    for (int itr = 0; itr < NREF; itr++) {
        if (tid < D) {
            float s = 0.0f;
            #pragma unroll 8
            for (int c = 0; c < D; c++) s += As[tid * PADE + c] * vv[c];
            uu[tid] = s;
            red[tid] = s * s;
        }
        __syncthreads();
        for (int r2 = 64; r2 > 0; r2 >>= 1) {
            if (tid < r2) red[tid] += red[tid + r2];
            __syncthreads();
        }
        float invn = rsqrtf(fmaxf(red[0], 1e-30f));
        __syncthreads();
        if (tid < D) vv[tid] = uu[tid] * invn;
        __syncthreads();
    }

    if (tid < D) {
        g_v1[tid] = vv[tid];
        float a = 0.0f;
        #pragma unroll 8
        for (int d2 = 0; d2 < D; d2++) a += vv[d2] * w1[d2 * D + tid];
        g_a1[tid] = a;
    }
}

// ---------------------------------------------------------------- fused enhancer, tf32 mma
__global__ __launch_bounds__(512, 1) void k_final3(const float* __restrict__ x,
                        const float* __restrict__ b1, const float* __restrict__ b2,
                        const float* __restrict__ w1, const float* __restrict__ w2,
                        float* __restrict__ out, int N, int nChunks) {
    extern __shared__ float sm[];
    float* xs  = sm;
    float* w1t = sm + 128 * PAD;
    float* w2t = w1t + 128 * PAD;
    float* q_s = w2t + 128 * PAD;
    float* sc_s = q_s + 128;
    __shared__ float v1_s[D], a1_s[D], be1_s[D], be2_s[D];

    int tid = threadIdx.x;
    int wid = tid >> 5, lane = tid & 31;
    int wm = wid >> 2, wn = wid & 3;
    int gid = lane >> 2, tg = lane & 3;
    int stride = gridDim.x;

    for (int idx = tid; idx < D * D; idx += 512) {
        int k = idx >> 7, n = idx & 127;
        w1t[n * PAD + k] = __uint_as_float(tf32cvt(w1[idx]));
        w2t[n * PAD + k] = __uint_as_float(tf32cvt(w2[idx]));
    }
    if (tid < D) {
        v1_s[tid] = g_v1[tid]; a1_s[tid] = g_a1[tid];
        be1_s[tid] = b1[tid];  be2_s[tid] = b2[tid];
    }

    float4 pf[8];
    int ch = blockIdx.x;
    if (ch < nChunks) {
        int R0 = ch * 128;
        #pragma unroll
        for (int u = 0; u < 8; u++) {
            int idx = tid + u * 512;
            int r = idx >> 5, c4 = idx & 31;
            int gr = R0 + r;
            pf[u] = (gr < N) ? ((const float4*)x)[(size_t)gr * 32 + c4]
                             : make_float4(0.f, 0.f, 0.f, 0.f);
        }
    }

    for (; ch < nChunks; ch += stride) {
        int R0 = ch * 128;
        __syncthreads();
        #pragma unroll
        for (int u = 0; u < 8; u++) {
            int idx = tid + u * 512;
            int r = idx >> 5, c4 = idx & 31;
            *(float4*)&xs[r * PAD + c4 * 4] = pf[u];
        }
        if (tid < 128) sc_s[tid] = (R0 + tid < N) ? g_scores[R0 + tid] : 0.0f;
        __syncthreads();
        if (tid < 128) {
            float q = 0.0f;
            #pragma unroll 8
            for (int d = 0; d < D; d++) q += xs[tid * PAD + d] * v1_s[d];
            q_s[tid] = q;
        }
        int nxt = ch + stride;
        if (nxt < nChunks) {
            int R1 = nxt * 128;
            #pragma unroll
            for (int u = 0; u < 8; u++) {
                int idx = tid + u * 512;
                int r = idx >> 5, c4 = idx & 31;
                int gr = R1 + r;
                pf[u] = (gr < N) ? ((const float4*)x)[(size_t)gr * 32 + c4]
                                 : make_float4(0.f, 0.f, 0.f, 0.f);
            }
        }
        __syncthreads();

        // GEMM1: z = x @ W1 (A hi/lo split)
        float cfr[2][4][4];
        #pragma unroll
        for (int mi = 0; mi < 2; mi++)
            #pragma unroll
            for (int ni = 0; ni < 4; ni++)
                #pragma unroll
                for (int j = 0; j < 4; j++) cfr[mi][ni][j] = 0.0f;

        #pragma unroll 2
        for (int ks = 0; ks < 16; ks++) {
            int k0 = ks * 8;
            uint32_t ah[2][4], al[2][4];
            #pragma unroll
            for (int mi = 0; mi < 2; mi++) {
                int r = wm * 32 + mi * 16 + gid;
                float f0 = xs[r * PAD + k0 + tg];
                float f1 = xs[(r + 8) * PAD + k0 + tg];
                float f2 = xs[r * PAD + k0 + tg + 4];
                float f3 = xs[(r + 8) * PAD + k0 + tg + 4];
                ah[mi][0] = tf32cvt(f0); al[mi][0] = tf32cvt(f0 - __uint_as_float(ah[mi][0]));
                ah[mi][1] = tf32cvt(f1); al[mi][1] = tf32cvt(f1 - __uint_as_float(ah[mi][1]));
                ah[mi][2] = tf32cvt(f2); al[mi][2] = tf32cvt(f2 - __uint_as_float(ah[mi][2]));
                ah[mi][3] = tf32cvt(f3); al[mi][3] = tf32cvt(f3 - __uint_as_float(ah[mi][3]));
            }
            uint32_t bh[4][2];
            #pragma unroll
            for (int ni = 0; ni < 4; ni++) {
                int c = wn * 32 + ni * 8 + gid;
                bh[ni][0] = __float_as_uint(w1t[c * PAD + k0 + tg]);
                bh[ni][1] = __float_as_uint(w1t[c * PAD + k0 + tg + 4]);
            }
            #pragma unroll
            for (int mi = 0; mi < 2; mi++)
                #pragma unroll
                for (int ni = 0; ni < 4; ni++) {
                    mma_tf32(cfr[mi][ni], ah[mi][0], ah[mi][1], ah[mi][2], ah[mi][3], bh[ni][0], bh[ni][1]);
                    mma_tf32(cfr[mi][ni], al[mi][0], al[mi][1], al[mi][2], al[mi][3], bh[ni][0], bh[ni][1]);
                }
        }
        __syncthreads();

        // epilogue1: relu(0.5*acc + 0.5*q*a1 + b1), store PRE-ROUNDED tf32
        #pragma unroll
        for (int mi = 0; mi < 2; mi++) {
            int r = wm * 32 + mi * 16 + gid;
            float qh0 = 0.5f * q_s[r], qh8 = 0.5f * q_s[r + 8];
            #pragma unroll
            for (int ni = 0; ni < 4; ni++) {
                int c = wn * 32 + ni * 8 + 2 * tg;
                float z00 = 0.5f * cfr[mi][ni][0] + qh0 * a1_s[c]     + be1_s[c];
                float z01 = 0.5f * cfr[mi][ni][1] + qh0 * a1_s[c + 1] + be1_s[c + 1];
                float z10 = 0.5f * cfr[mi][ni][2] + qh8 * a1_s[c]     + be1_s[c];
                float z11 = 0.5f * cfr[mi][ni][3] + qh8 * a1_s[c + 1] + be1_s[c + 1];
                float2 p0 = make_float2(__uint_as_float(tf32cvt(fmaxf(z00, 0.f))),
                                        __uint_as_float(tf32cvt(fmaxf(z01, 0.f))));
                float2 p1 = make_float2(__uint_as_float(tf32cvt(fmaxf(z10, 0.f))),
                                        __uint_as_float(tf32cvt(fmaxf(z11, 0.f))));
                *(float2*)&xs[r * PAD + c]       = p0;
                *(float2*)&xs[(r + 8) * PAD + c] = p1;
            }
        }
        __syncthreads();

        // GEMM2: single pass, A pre-rounded
        #pragma unroll
        for (int mi = 0; mi < 2; mi++)
            #pragma unroll
            for (int ni = 0; ni < 4; ni++)
                #pragma unroll
                for (int j = 0; j < 4; j++) cfr[mi][ni][j] = 0.0f;

        #pragma unroll 2
        for (int ks = 0; ks < 16; ks++) {
            int k0 = ks * 8;
            uint32_t a2[2][4];
            #pragma unroll
            for (int mi = 0; mi < 2; mi++) {
                int r = wm * 32 + mi * 16 + gid;
                a2[mi][0] = __float_as_uint(xs[r * PAD + k0 + tg]);
                a2[mi][1] = __float_as_uint(xs[(r + 8) * PAD + k0 + tg]);
                a2[mi][2] = __float_as_uint(xs[r * PAD + k0 + tg + 4]);
                a2[mi][3] = __float_as_uint(xs[(r + 8) * PAD + k0 + tg + 4]);
            }
            uint32_t bh[4][2];
            #pragma unroll
            for (int ni = 0; ni < 4; ni++) {
                int c = wn * 32 + ni * 8 + gid;
                bh[ni][0] = __float_as_uint(w2t[c * PAD + k0 + tg]);
                bh[ni][1] = __float_as_uint(w2t[c * PAD + k0 + tg + 4]);
            }
            #pragma unroll
            for (int mi = 0; mi < 2; mi++)
                #pragma unroll
                for (int ni = 0; ni < 4; ni++)
                    mma_tf32(cfr[mi][ni], a2[mi][0], a2[mi][1], a2[mi][2], a2[mi][3], bh[ni][0], bh[ni][1]);
        }

        // epilogue2
        #pragma unroll
        for (int mi = 0; mi < 2; mi++) {
            int r = wm * 32 + mi * 16 + gid;
            #pragma unroll
            for (int rr = 0; rr < 2; rr++) {
                int row = r + rr * 8;
                int gr = R0 + row;
                if (gr >= N) continue;
                float sc = sc_s[row], qh = 0.5f * q_s[row];
                #pragma unroll
                for (int ni = 0; ni < 4; ni++) {
                    int c = wn * 32 + ni * 8 + 2 * tg;
                    float e0 = cfr[mi][ni][rr * 2 + 0];
                    float e1 = cfr[mi][ni][rr * 2 + 1];
                    float2 xv = ((const float2*)x)[(size_t)gr * 64 + (c >> 1)];
                    float o0 = (e0 + be2_s[c])     * sc + 0.5f * xv.x + qh * v1_s[c];
                    float o1 = (e1 + be2_s[c + 1]) * sc + 0.5f * xv.y + qh * v1_s[c + 1];
                    ((float2*)out)[(size_t)gr * 64 + (c >> 1)] = make_float2(o0, o1);
                }
            }
        }
    }
}

// ---------------------------------------------------------------- launch
extern "C" void kernel_launch(void* const* d_in, const int* in_sizes, int n_in,
                              void* d_out, int out_size) {
    const float* x       = (const float*)d_in[0];
    const void*  ei      = d_in[1];
    const float* ew      = (const float*)d_in[2];
    const float* w_gcn   = (const float*)d_in[3];
    const float* b_gcn   = (const float*)d_in[4];
    const float* w_score = (const float*)d_in[5];
    const float* b_score = (const float*)d_in[6];
    const float* alpha   = (const float*)d_in[7];
    const float* beta    = (const float*)d_in[8];
    const float* w_e1    = (const float*)d_in[9];
    const float* b_e1    = (const float*)d_in[10];
    const float* w_e2    = (const float*)d_in[11];
    const float* b_e2    = (const float*)d_in[12];
    float* out = (float*)d_out;

    int N = in_sizes[0] / D;
    int E = in_sizes[2];
    int nChunks = (N + 127) / 128;
    int NB = (N + 255) / 256;
    int E2 = (E + 1) / 2;
    int EB2 = (E2 + 255) / 256;
    int ZB = (N + 255) / 256;
    int PB = (N * 32 + 255) / 256;

    const int SMG = 2 * 128 * PADG * 4;
    const int SMF = (3 * 128 * PAD + 256) * 4;
    const int SMP = (128 * PAD) * 4;

    static int init_done = 0;
    static cudaStream_t s1;
    static cudaEvent_t evFork, evScores, evGate;
    if (!init_done) {
        cudaFuncSetAttribute(k_G,      cudaFuncAttributeMaxDynamicSharedMemorySize, SMG);
        cudaFuncSetAttribute(k_power,  cudaFuncAttributeMaxDynamicSharedMemorySize, SMP);
        cudaFuncSetAttribute(k_final3, cudaFuncAttributeMaxDynamicSharedMemorySize, SMF);
        cudaStreamCreateWithFlags(&s1, cudaStreamNonBlocking);
        cudaEventCreateWithFlags(&evFork,   cudaEventDisableTiming);
        cudaEventCreateWithFlags(&evScores, cudaEventDisableTiming);
        cudaEventCreateWithFlags(&evGate,   cudaEventDisableTiming);
        init_done = 1;
    }

    // fork s1 (carries the whole prologue + edge chain, off the s0 critical path)
    cudaEventRecord(evFork, 0);
    cudaStreamWaitEvent(s1, evFork, 0);

    k_pre2<<<ZB + 2, 256, 0, s1>>>((const long long*)ei, E, N, w_gcn, b_gcn, w_score, b_score, ZB);
    k_deg<<<EB2, 256, 0, s1>>>(ei, E);
    k_p<<<PB, 256, 0, s1>>>(x, N);
    k_dinv<<<NB, 256, 0, s1>>>(N);
    k_edge<<<EB2, 256, 0, s1>>>(ei, E);
    k_scores<<<NB, 256, 0, s1>>>(N);
    cudaEventRecord(evScores, s1);
    k_gate<<<EB2, 256, 0, s1>>>(ei, ew, alpha, beta, out + (size_t)N * D, E);   // overlaps k_final3
    cudaEventRecord(evGate, s1);

    // s0 critical path: tiny zero -> Gram -> power -> final
    k_zeroG<<<16, 256>>>();
    k_G<<<148, 512, SMG>>>(x, N, nChunks);
    k_power<<<PWB, 1024, SMP>>>(w_e1);

    cudaStreamWaitEvent(0, evScores, 0);
    k_final3<<<148, 512, SMF>>>(x, b_e1, b_e2, w_e1, w_e2, out, N, nChunks);
    cudaStreamWaitEvent(0, evGate, 0);   // join s1 fully for capture
}

// round 12
// speedup vs baseline: 1.1202x; 1.0647x over previous
#include <cuda_runtime.h>
#include <math.h>
#include <stdint.h>

#define D 128
#define PAD 132            // k_final/k_power smem row pitch (floats)
#define PADG 136           // k_G pitch: mod 32 == 8 -> conflict-free mma fragment loads
#define PADE 129
#define NMAX 65536
#define NSQ 10
#define NREF 5
#define PWB 16             // k_power blocks

static __device__ int   g_degi[NMAX];
static __device__ float g_dinv[NMAX];
static __device__ float g_p[NMAX];
static __device__ float g_dp[NMAX];
static __device__ float g_sacc[NMAX];
static __device__ float g_scores[NMAX];
static __device__ __align__(16) float g_G[D * D];
static __device__ __align__(16) float g_Ea[D * D];
static __device__ __align__(16) float g_Eb[D * D];
static __device__ float g_v1[D];
static __device__ float g_a1[D];
static __device__ float g_wv[D];
static __device__ float g_bg;
static __device__ int   g_i32;
static __device__ int   g_bar;

// ---------------------------------------------------------------- utilities
__device__ __forceinline__ float sigmoidf_(float z) {
    return 1.0f / (1.0f + expf(-z));
}

__device__ __forceinline__ unsigned smem_u32(const void* p) {
    return (unsigned)__cvta_generic_to_shared(p);
}
__device__ __forceinline__ void cp16(unsigned s, const void* g) {
    asm volatile("cp.async.cg.shared.global [%0], [%1], 16;\n" :: "r"(s), "l"(g));
}
#define CP_COMMIT() asm volatile("cp.async.commit_group;\n" ::)
#define CP_WAIT(n)  asm volatile("cp.async.wait_group %0;\n" :: "n"(n))

__device__ __forceinline__ uint32_t tf32cvt(float f) {
    uint32_t u;
    asm("cvt.rna.tf32.f32 %0, %1;" : "=r"(u) : "f"(f));
    return u;
}

__device__ __forceinline__ void mma_tf32(float* c, uint32_t a0, uint32_t a1, uint32_t a2, uint32_t a3,
                                         uint32_t b0, uint32_t b1) {
    asm volatile("mma.sync.aligned.m16n8k8.row.col.f32.tf32.tf32.f32 "
                 "{%0,%1,%2,%3}, {%4,%5,%6,%7}, {%8,%9}, {%0,%1,%2,%3};"
                 : "+f"(c[0]), "+f"(c[1]), "+f"(c[2]), "+f"(c[3])
                 : "r"(a0), "r"(a1), "r"(a2), "r"(a3), "r"(b0), "r"(b1));
}

// L2-coherent float4 load for cross-block exchange in k_power.
__device__ __forceinline__ float4 ldcg4(const float4* p) {
    float4 v;
    asm volatile("ld.global.cg.v4.f32 {%0,%1,%2,%3}, [%4];"
                 : "=f"(v.x), "=f"(v.y), "=f"(v.z), "=f"(v.w) : "l"(p));
    return v;
}

// ---------------------------------------------------------------- s0 micro-prologue: zero g_G + g_bar
__global__ void k_zeroG() {
    int i = blockIdx.x * 256 + threadIdx.x;     // 16*256 = 4096 = D*D/4
    ((float4*)g_G)[i] = make_float4(0.f, 0.f, 0.f, 0.f);
    if (i == 0) g_bar = 0;
}

// ---------------------------------------------------------------- s1 prologue: zero degi + detect + wv/bg
__global__ void k_pre2(const long long* ei, int E, int N,
                       const float* __restrict__ wg, const float* __restrict__ bgc,
                       const float* __restrict__ ws, const float* __restrict__ bs, int ZB) {
    int b = blockIdx.x, t = threadIdx.x;
    if (b < ZB) {
        int i = b * 256 + t;
        if (i < N) g_degi[i] = 0;
    } else if (b == ZB) {
        __shared__ int flag;
        if (t == 0) flag = 0;
        __syncthreads();
        int n = E < 1024 ? E : 1024;
        for (int e = t; e < n; e += 256)
            if ((unsigned long long)ei[e] >= (unsigned long long)N) flag = 1;
        __syncthreads();
        if (t == 0) g_i32 = flag;
    } else {
        __shared__ float wss[D];
        if (t < D) wss[t] = ws[t];
        __syncthreads();
        if (t < D) {
            float s = 0.0f;
            #pragma unroll 8
            for (int m = 0; m < D; m++) s += wg[t * D + m] * wss[m];
            g_wv[t] = s;
        }
        if (t == 0) {
            float bsum = bs[0];
            for (int m = 0; m < D; m++) bsum += bgc[m] * wss[m];
            g_bg = bsum;
        }
    }
}

// ---------------------------------------------------------------- edge/score chain
__global__ void k_p(const float* __restrict__ x, int N) {
    int w = (blockIdx.x * blockDim.x + threadIdx.x) >> 5;
    int lane = threadIdx.x & 31;
    if (w >= N) return;
    float4 xv = ((const float4*)x)[(size_t)w * 32 + lane];
    float4 wv = *(const float4*)&g_wv[lane * 4];
    float s = xv.x * wv.x + xv.y * wv.y + xv.z * wv.z + xv.w * wv.w;
    #pragma unroll
    for (int o = 16; o; o >>= 1) s += __shfl_xor_sync(0xffffffffu, s, o);
    if (lane == 0) g_p[w] = s;
}

__global__ void k_deg(const void* ei, int E) {
    int e = (blockIdx.x * 256 + threadIdx.x) * 2;
    if (e >= E) return;
    if (g_i32) {
        const int* dst = (const int*)ei + E;
        atomicAdd(&g_degi[dst[e]], 1);
        if (e + 1 < E) atomicAdd(&g_degi[dst[e + 1]], 1);
    } else {
        const long long* dst = (const long long*)ei + E;
        if (e + 1 < E) {
            longlong2 d = *(const longlong2*)&dst[e];
            atomicAdd(&g_degi[(int)d.x], 1);
            atomicAdd(&g_degi[(int)d.y], 1);
        } else {
            atomicAdd(&g_degi[(int)dst[e]], 1);
        }
    }
}

// dinv, dp = dinv*p; sacc initialized with self-loop term dp[i] (so sacc_final = dinv*(sum dp[s] + dp[i]))
__global__ void k_dinv(int N) {
    int i = blockIdx.x * 256 + threadIdx.x;
    if (i >= N) return;
    float di = rsqrtf((float)(g_degi[i] + 1));
    float dpv = di * g_p[i];
    g_dinv[i] = di;
    g_dp[i] = dpv;
    g_sacc[i] = dpv;
}

// sacc[t] += dp[s]  (one random gather per edge)
__global__ void k_edge(const void* ei, int E) {
    int e = (blockIdx.x * 256 + threadIdx.x) * 2;
    if (e >= E) return;
    if (g_i32) {
        const int* src = (const int*)ei;
        const int* dst = src + E;
        #pragma unroll
        for (int u = 0; u < 2; u++) {
            if (e + u >= E) break;
            atomicAdd(&g_sacc[dst[e + u]], g_dp[src[e + u]]);
        }
    } else {
        const long long* src = (const long long*)ei;
        const long long* dst = src + E;
        if (e + 1 < E) {
            longlong2 sv = *(const longlong2*)&src[e];
            longlong2 dv = *(const longlong2*)&dst[e];
            atomicAdd(&g_sacc[(int)dv.x], g_dp[(int)sv.x]);
            atomicAdd(&g_sacc[(int)dv.y], g_dp[(int)sv.y]);
        } else {
            atomicAdd(&g_sacc[(int)dst[e]], g_dp[(int)src[e]]);
        }
    }
}

__global__ void k_scores(int N) {
    int i = blockIdx.x * 256 + threadIdx.x;
    if (i >= N) return;
    g_scores[i] = sigmoidf_(g_dinv[i] * g_sacc[i] + g_bg);
}

__global__ void k_gate(const void* ei, const float* __restrict__ ew,
                       const float* __restrict__ al, const float* __restrict__ be,
                       float* __restrict__ out, int E) {
    int e = (blockIdx.x * 256 + threadIdx.x) * 2;
    if (e >= E) return;
    float a_ = al[0], b_ = be[0];
    if (g_i32) {
        const int* src = (const int*)ei;
        const int* dst = src + E;
        #pragma unroll
        for (int u = 0; u < 2; u++) {
            if (e + u >= E) break;
            int s = src[e + u], t = dst[e + u];
            float z = a_ * (g_scores[s] + g_scores[t]) + b_;
            out[e + u] = ew[e + u] * sigmoidf_(z);
        }
    } else {
        const long long* src = (const long long*)ei;
        const long long* dst = src + E;
        if (e + 1 < E) {
            longlong2 sv = *(const longlong2*)&src[e];
            longlong2 dv = *(const longlong2*)&dst[e];
            float2 w = *(const float2*)&ew[e];
            float z0 = a_ * (g_scores[(int)sv.x] + g_scores[(int)dv.x]) + b_;
            float z1 = a_ * (g_scores[(int)sv.y] + g_scores[(int)dv.y]) + b_;
            float2 o = make_float2(w.x * sigmoidf_(z0), w.y * sigmoidf_(z1));
            *(float2*)&out[e] = o;
        } else {
            int s = (int)src[e], t = (int)dst[e];
            float z = a_ * (g_scores[s] + g_scores[t]) + b_;
            out[e] = ew[e] * sigmoidf_(z);
        }
    }
}

// ---------------------------------------------------------------- Gram: tf32 mma, 3-pass hi/lo split
__global__ __launch_bounds__(512, 1) void k_G(const float* __restrict__ x, int N, int nChunks) {
    extern __shared__ float sm[];
    float* bufs[2] = { sm, sm + 128 * PADG };
    int tid = threadIdx.x;
    int wid = tid >> 5, lane = tid & 31;
    int wm = wid >> 2, wn = wid & 3;
    int gid = lane >> 2, tg = lane & 3;
    int m0 = wm * 32, n0 = wn * 32;
    int stride = gridDim.x;

    float acc[2][4][4];
    #pragma unroll
    for (int mi = 0; mi < 2; mi++)
        #pragma unroll
        for (int ni = 0; ni < 4; ni++)
            #pragma unroll
            for (int j = 0; j < 4; j++) acc[mi][ni][j] = 0.0f;

    int ch = blockIdx.x;
    if (ch < nChunks) {
        int R0 = ch * 128;
        if (R0 + 128 <= N) {
            #pragma unroll
            for (int u = 0; u < 8; u++) {
                int idx = tid + u * 512;
                int r = idx >> 5, c4 = idx & 31;
                cp16(smem_u32(&bufs[0][r * PADG + c4 * 4]), &x[((size_t)(R0 + r)) * 128 + c4 * 4]);
            }
        } else {
            #pragma unroll
            for (int u = 0; u < 8; u++) {
                int idx = tid + u * 512;
                int r = idx >> 5, c4 = idx & 31;
                int gr = R0 + r;
                float4 v = (gr < N) ? ((const float4*)x)[(size_t)gr * 32 + c4]
                                    : make_float4(0.f, 0.f, 0.f, 0.f);
                *(float4*)&bufs[0][r * PADG + c4 * 4] = v;
            }
        }
        CP_COMMIT();
    }

    int cur = 0;
    for (; ch < nChunks; ch += stride) {
        int nxt = ch + stride;
        if (nxt < nChunks) {
            float* bn = bufs[cur ^ 1];
            int R1 = nxt * 128;
            if (R1 + 128 <= N) {
                #pragma unroll
                for (int u = 0; u < 8; u++) {
                    int idx = tid + u * 512;
                    int r = idx >> 5, c4 = idx & 31;
                    cp16(smem_u32(&bn[r * PADG + c4 * 4]), &x[((size_t)(R1 + r)) * 128 + c4 * 4]);
                }
            } else {
                #pragma unroll
                for (int u = 0; u < 8; u++) {
                    int idx = tid + u * 512;
                    int r = idx >> 5, c4 = idx & 31;
                    int gr = R1 + r;
                    float4 v = (gr < N) ? ((const float4*)x)[(size_t)gr * 32 + c4]
                                        : make_float4(0.f, 0.f, 0.f, 0.f);
                    *(float4*)&bn[r * PADG + c4 * 4] = v;
                }
            }
            CP_COMMIT();
            CP_WAIT(1);
        } else {
            CP_WAIT(0);
        }
        __syncthreads();
        const float* bc = bufs[cur];

        #pragma unroll 2
        for (int ks = 0; ks < 16; ks++) {
            int k0 = ks * 8;
            uint32_t ah[2][4], al[2][4];
            #pragma unroll
            for (int mi = 0; mi < 2; mi++) {
                int i0 = m0 + mi * 16 + gid;
                float f0 = bc[(k0 + tg) * PADG + i0];
                float f1 = bc[(k0 + tg) * PADG + i0 + 8];
                float f2 = bc[(k0 + tg + 4) * PADG + i0];
                float f3 = bc[(k0 + tg + 4) * PADG + i0 + 8];
                ah[mi][0] = tf32cvt(f0); al[mi][0] = tf32cvt(f0 - __uint_as_float(ah[mi][0]));
                ah[mi][1] = tf32cvt(f1); al[mi][1] = tf32cvt(f1 - __uint_as_float(ah[mi][1]));
                ah[mi][2] = tf32cvt(f2); al[mi][2] = tf32cvt(f2 - __uint_as_float(ah[mi][2]));
                ah[mi][3] = tf32cvt(f3); al[mi][3] = tf32cvt(f3 - __uint_as_float(ah[mi][3]));
            }
            uint32_t bh[4][2], bl[4][2];
            #pragma unroll
            for (int ni = 0; ni < 4; ni++) {
                int j0 = n0 + ni * 8 + gid;
                float g0 = bc[(k0 + tg) * PADG + j0];
                float g1 = bc[(k0 + tg + 4) * PADG + j0];
                bh[ni][0] = tf32cvt(g0); bl[ni][0] = tf32cvt(g0 - __uint_as_float(bh[ni][0]));
                bh[ni][1] = tf32cvt(g1); bl[ni][1] = tf32cvt(g1 - __uint_as_float(bh[ni][1]));
            }
            #pragma unroll
            for (int mi = 0; mi < 2; mi++)
                #pragma unroll
                for (int ni = 0; ni < 4; ni++) {
                    mma_tf32(acc[mi][ni], ah[mi][0], ah[mi][1], ah[mi][2], ah[mi][3], bh[ni][0], bh[ni][1]);
                    mma_tf32(acc[mi][ni], ah[mi][0], ah[mi][1], ah[mi][2], ah[mi][3], bl[ni][0], bl[ni][1]);
                    mma_tf32(acc[mi][ni], al[mi][0], al[mi][1], al[mi][2], al[mi][3], bh[ni][0], bh[ni][1]);
                }
        }
        cur ^= 1;
        __syncthreads();
    }
    #pragma unroll
    for (int mi = 0; mi < 2; mi++)
        #pragma unroll
        for (int ni = 0; ni < 4; ni++) {
            int r = m0 + mi * 16 + gid, c = n0 + ni * 8 + 2 * tg;
            atomicAdd(&g_G[r * D + c],           acc[mi][ni][0]);
            atomicAdd(&g_G[r * D + c + 1],       acc[mi][ni][1]);
            atomicAdd(&g_G[(r + 8) * D + c],     acc[mi][ni][2]);
            atomicAdd(&g_G[(r + 8) * D + c + 1], acc[mi][ni][3]);
        }
}

// ---------------------------------------------------------------- fused power iteration + extract
__global__ __launch_bounds__(1024, 1) void k_power(const float* __restrict__ w1) {
    extern __shared__ float sm[];
    float* As = sm;
    int tid = threadIdx.x;
    int ty = tid >> 7;
    int tx = tid & 127;
    int wid = tid >> 5, lane = tid & 31;
    int r = blockIdx.x * 8 + ty;
    __shared__ float redm[32];

    for (int it = 0; it < NSQ; it++) {
        const float* in = (it == 0) ? g_G : ((it & 1) ? g_Ea : g_Eb);
        float* outp = (it & 1) ? g_Eb : g_Ea;
        float m = 0.0f;
        #pragma unroll
        for (int u = 0; u < 4; u++) {
            int idx = tid + u * 1024;
            int rr = idx >> 5, c4 = idx & 31;
            float4 v = ldcg4(&((const float4*)in)[idx]);
            *(float4*)&As[rr * PAD + c4 * 4] = v;
            m = fmaxf(m, fmaxf(fmaxf(fabsf(v.x), fabsf(v.y)), fmaxf(fabsf(v.z), fabsf(v.w))));
        }
        #pragma unroll
        for (int o = 16; o; o >>= 1) m = fmaxf(m, __shfl_xor_sync(0xffffffffu, m, o));
        if (lane == 0) redm[wid] = m;
        __syncthreads();
        if (tid < 32) {
            float mm = redm[tid];
            #pragma unroll
            for (int o = 16; o; o >>= 1) mm = fmaxf(mm, __shfl_xor_sync(0xffffffffu, mm, o));
            if (tid == 0) redm[0] = mm;
        }
        __syncthreads();
        float inv = 1.0f / redm[0];
        float inv2 = inv * inv;

        float acc = 0.0f;
        #pragma unroll 8
        for (int k = 0; k < D; k++) acc += As[r * PAD + k] * As[k * PAD + tx];
        outp[r * D + tx] = acc * inv2;

        __threadfence();
        __syncthreads();
        if (tid == 0) {
            atomicAdd(&g_bar, 1);
            int target = PWB * (it + 1);
            while (*(volatile int*)&g_bar < target) { __nanosleep(64); }
            __threadfence();
        }
        __syncthreads();
    }

    if (blockIdx.x != 0) return;

    float* vv = sm + D * PADE;
    float* uu = vv + D;
    float* red = uu + D;
    __shared__ int redi[128];
    __shared__ int jm;
    const float* P = (NSQ & 1) ? g_Eb : g_Ea;
    for (int idx4 = tid; idx4 < D * D / 4; idx4 += 1024) {
        float4 v = ldcg4(&((const float4*)P)[idx4]);
        int idx = idx4 * 4;
        int rr = idx >> 7, c = idx & 127;
        As[rr * PADE + c + 0] = v.x;
        As[rr * PADE + c + 1] = v.y;
        As[rr * PADE + c + 2] = v.z;
        As[rr * PADE + c + 3] = v.w;
    }
    __syncthreads();
    if (tid < D) { red[tid] = As[tid * PADE + tid]; redi[tid] = tid; }
    __syncthreads();
    for (int s = 64; s > 0; s >>= 1) {
        if (tid < s && red[tid + s] > red[tid]) { red[tid] = red[tid + s]; redi[tid] = redi[tid + s]; }
        __syncthreads();
    }
    if (tid == 0) jm = redi[0];
    __syncthreads();
    if (tid < D) vv[tid] = As[jm * PADE + tid];
    __syncthreads();

    for (int itr = 0; itr < NREF; itr++) {
        if (tid < D) {
            float s = 0.0f;
            #pragma unroll 8
            for (int c = 0; c < D; c++) s += As[tid * PADE + c] * vv[c];
            uu[tid] = s;
            red[tid] = s * s;
        }
        __syncthreads();
        for (int r2 = 64; r2 > 0; r2 >>= 1) {
            if (tid < r2) red[tid] += red[tid + r2];
            __syncthreads();
        }
        float invn = rsqrtf(fmaxf(red[0], 1e-30f));
        __syncthreads();
        if (tid < D) vv[tid] = uu[tid] * invn;
        __syncthreads();
    }

    if (tid < D) {
        g_v1[tid] = vv[tid];
        float a = 0.0f;
        #pragma unroll 8
        for (int d2 = 0; d2 < D; d2++) a += vv[d2] * w1[d2 * D + tid];
        g_a1[tid] = a;
    }
}

// ---------------------------------------------------------------- fused enhancer, tf32 mma (GEMM1 single-pass)
__global__ __launch_bounds__(512, 1) void k_final3(const float* __restrict__ x,
                        const float* __restrict__ b1, const float* __restrict__ b2,
                        const float* __restrict__ w1, const float* __restrict__ w2,
                        float* __restrict__ out, int N, int nChunks) {
    extern __shared__ float sm[];
    float* xs  = sm;
    float* w1t = sm + 128 * PAD;
    float* w2t = w1t + 128 * PAD;
    float* q_s = w2t + 128 * PAD;
    float* sc_s = q_s + 128;
    __shared__ float v1_s[D], a1_s[D], be1_s[D], be2_s[D];

    int tid = threadIdx.x;
    int wid = tid >> 5, lane = tid & 31;
    int wm = wid >> 2, wn = wid & 3;
    int gid = lane >> 2, tg = lane & 3;
    int stride = gridDim.x;

    for (int idx = tid; idx < D * D; idx += 512) {
        int k = idx >> 7, n = idx & 127;
        w1t[n * PAD + k] = __uint_as_float(tf32cvt(w1[idx]));
        w2t[n * PAD + k] = __uint_as_float(tf32cvt(w2[idx]));
    }
    if (tid < D) {
        v1_s[tid] = g_v1[tid]; a1_s[tid] = g_a1[tid];
        be1_s[tid] = b1[tid];  be2_s[tid] = b2[tid];
    }

    float4 pf[8];
    int ch = blockIdx.x;
    if (ch < nChunks) {
        int R0 = ch * 128;
        #pragma unroll
        for (int u = 0; u < 8; u++) {
            int idx = tid + u * 512;
            int r = idx >> 5, c4 = idx & 31;
            int gr = R0 + r;
            pf[u] = (gr < N) ? ((const float4*)x)[(size_t)gr * 32 + c4]
                             : make_float4(0.f, 0.f, 0.f, 0.f);
        }
    }

    for (; ch < nChunks; ch += stride) {
        int R0 = ch * 128;
        __syncthreads();
        #pragma unroll
        for (int u = 0; u < 8; u++) {
            int idx = tid + u * 512;
            int r = idx >> 5, c4 = idx & 31;
            *(float4*)&xs[r * PAD + c4 * 4] = pf[u];
        }
        if (tid < 128) sc_s[tid] = (R0 + tid < N) ? g_scores[R0 + tid] : 0.0f;
        __syncthreads();
        if (tid < 128) {
            float q = 0.0f;
            #pragma unroll 8
            for (int d = 0; d < D; d++) q += xs[tid * PAD + d] * v1_s[d];
            q_s[tid] = q;
        }
        int nxt = ch + stride;
        if (nxt < nChunks) {
            int R1 = nxt * 128;
            #pragma unroll
            for (int u = 0; u < 8; u++) {
                int idx = tid + u * 512;
                int r = idx >> 5, c4 = idx & 31;
                int gr = R1 + r;
                pf[u] = (gr < N) ? ((const float4*)x)[(size_t)gr * 32 + c4]
                                 : make_float4(0.f, 0.f, 0.f, 0.f);
            }
        }
        __syncthreads();

        // GEMM1: z = x @ W1 (single-pass tf32; A rounded once)
        float cfr[2][4][4];
        #pragma unroll
        for (int mi = 0; mi < 2; mi++)
            #pragma unroll
            for (int ni = 0; ni < 4; ni++)
                #pragma unroll
                for (int j = 0; j < 4; j++) cfr[mi][ni][j] = 0.0f;

        #pragma unroll 2
        for (int ks = 0; ks < 16; ks++) {
            int k0 = ks * 8;
            uint32_t ah[2][4];
            #pragma unroll
            for (int mi = 0; mi < 2; mi++) {
                int r = wm * 32 + mi * 16 + gid;
                ah[mi][0] = tf32cvt(xs[r * PAD + k0 + tg]);
                ah[mi][1] = tf32cvt(xs[(r + 8) * PAD + k0 + tg]);
                ah[mi][2] = tf32cvt(xs[r * PAD + k0 + tg + 4]);
                ah[mi][3] = tf32cvt(xs[(r + 8) * PAD + k0 + tg + 4]);
            }
            uint32_t bh[4][2];
            #pragma unroll
            for (int ni = 0; ni < 4; ni++) {
                int c = wn * 32 + ni * 8 + gid;
                bh[ni][0] = __float_as_uint(w1t[c * PAD + k0 + tg]);
                bh[ni][1] = __float_as_uint(w1t[c * PAD + k0 + tg + 4]);
            }
            #pragma unroll
            for (int mi = 0; mi < 2; mi++)
                #pragma unroll
                for (int ni = 0; ni < 4; ni++)
                    mma_tf32(cfr[mi][ni], ah[mi][0], ah[mi][1], ah[mi][2], ah[mi][3], bh[ni][0], bh[ni][1]);
        }
        __syncthreads();

        // epilogue1: relu(0.5*acc + 0.5*q*a1 + b1), store PRE-ROUNDED tf32
        #pragma unroll
        for (int mi = 0; mi < 2; mi++) {
            int r = wm * 32 + mi * 16 + gid;
            float qh0 = 0.5f * q_s[r], qh8 = 0.5f * q_s[r + 8];
            #pragma unroll
            for (int ni = 0; ni < 4; ni++) {
                int c = wn * 32 + ni * 8 + 2 * tg;
                float z00 = 0.5f * cfr[mi][ni][0] + qh0 * a1_s[c]     + be1_s[c];
                float z01 = 0.5f * cfr[mi][ni][1] + qh0 * a1_s[c + 1] + be1_s[c + 1];
                float z10 = 0.5f * cfr[mi][ni][2] + qh8 * a1_s[c]     + be1_s[c];
                float z11 = 0.5f * cfr[mi][ni][3] + qh8 * a1_s[c + 1] + be1_s[c + 1];
                float2 p0 = make_float2(__uint_as_float(tf32cvt(fmaxf(z00, 0.f))),
                                        __uint_as_float(tf32cvt(fmaxf(z01, 0.f))));
                float2 p1 = make_float2(__uint_as_float(tf32cvt(fmaxf(z10, 0.f))),
                                        __uint_as_float(tf32cvt(fmaxf(z11, 0.f))));
                *(float2*)&xs[r * PAD + c]       = p0;
                *(float2*)&xs[(r + 8) * PAD + c] = p1;
            }
        }
        __syncthreads();

        // GEMM2: single pass, A pre-rounded
        #pragma unroll
        for (int mi = 0; mi < 2; mi++)
            #pragma unroll
            for (int ni = 0; ni < 4; ni++)
                #pragma unroll
                for (int j = 0; j < 4; j++) cfr[mi][ni][j] = 0.0f;

        #pragma unroll 2
        for (int ks = 0; ks < 16; ks++) {
            int k0 = ks * 8;
            uint32_t a2[2][4];
            #pragma unroll
            for (int mi = 0; mi < 2; mi++) {
                int r = wm * 32 + mi * 16 + gid;
                a2[mi][0] = __float_as_uint(xs[r * PAD + k0 + tg]);
                a2[mi][1] = __float_as_uint(xs[(r + 8) * PAD + k0 + tg]);
                a2[mi][2] = __float_as_uint(xs[r * PAD + k0 + tg + 4]);
                a2[mi][3] = __float_as_uint(xs[(r + 8) * PAD + k0 + tg + 4]);
            }
            uint32_t bh[4][2];
            #pragma unroll
            for (int ni = 0; ni < 4; ni++) {
                int c = wn * 32 + ni * 8 + gid;
                bh[ni][0] = __float_as_uint(w2t[c * PAD + k0 + tg]);
                bh[ni][1] = __float_as_uint(w2t[c * PAD + k0 + tg + 4]);
            }
            #pragma unroll
            for (int mi = 0; mi < 2; mi++)
                #pragma unroll
                for (int ni = 0; ni < 4; ni++)
                    mma_tf32(cfr[mi][ni], a2[mi][0], a2[mi][1], a2[mi][2], a2[mi][3], bh[ni][0], bh[ni][1]);
        }

        // epilogue2
        #pragma unroll
        for (int mi = 0; mi < 2; mi++) {
            int r = wm * 32 + mi * 16 + gid;
            #pragma unroll
            for (int rr = 0; rr < 2; rr++) {
                int row = r + rr * 8;
                int gr = R0 + row;
                if (gr >= N) continue;
                float sc = sc_s[row], qh = 0.5f * q_s[row];
                #pragma unroll
                for (int ni = 0; ni < 4; ni++) {
                    int c = wn * 32 + ni * 8 + 2 * tg;
                    float e0 = cfr[mi][ni][rr * 2 + 0];
                    float e1 = cfr[mi][ni][rr * 2 + 1];
                    float2 xv = ((const float2*)x)[(size_t)gr * 64 + (c >> 1)];
                    float o0 = (e0 + be2_s[c])     * sc + 0.5f * xv.x + qh * v1_s[c];
                    float o1 = (e1 + be2_s[c + 1]) * sc + 0.5f * xv.y + qh * v1_s[c + 1];
                    ((float2*)out)[(size_t)gr * 64 + (c >> 1)] = make_float2(o0, o1);
                }
            }
        }
    }
}

// ---------------------------------------------------------------- launch
extern "C" void kernel_launch(void* const* d_in, const int* in_sizes, int n_in,
                              void* d_out, int out_size) {
    const float* x       = (const float*)d_in[0];
    const void*  ei      = d_in[1];
    const float* ew      = (const float*)d_in[2];
    const float* w_gcn   = (const float*)d_in[3];
    const float* b_gcn   = (const float*)d_in[4];
    const float* w_score = (const float*)d_in[5];
    const float* b_score = (const float*)d_in[6];
    const float* alpha   = (const float*)d_in[7];
    const float* beta    = (const float*)d_in[8];
    const float* w_e1    = (const float*)d_in[9];
    const float* b_e1    = (const float*)d_in[10];
    const float* w_e2    = (const float*)d_in[11];
    const float* b_e2    = (const float*)d_in[12];
    float* out = (float*)d_out;

    int N = in_sizes[0] / D;
    int E = in_sizes[2];
    int nChunks = (N + 127) / 128;
    int NB = (N + 255) / 256;
    int E2 = (E + 1) / 2;
    int EB2 = (E2 + 255) / 256;
    int ZB = (N + 255) / 256;
    int PB = (N * 32 + 255) / 256;

    const int SMG = 2 * 128 * PADG * 4;
    const int SMF = (3 * 128 * PAD + 256) * 4;
    const int SMP = (128 * PAD) * 4;

    static int init_done = 0;
    static cudaStream_t s1, s2;
    static cudaEvent_t evFork, evScores, evGate, evPre, evP;
    if (!init_done) {
        cudaFuncSetAttribute(k_G,      cudaFuncAttributeMaxDynamicSharedMemorySize, SMG);
        cudaFuncSetAttribute(k_power,  cudaFuncAttributeMaxDynamicSharedMemorySize, SMP);
        cudaFuncSetAttribute(k_final3, cudaFuncAttributeMaxDynamicSharedMemorySize, SMF);
        cudaStreamCreateWithFlags(&s1, cudaStreamNonBlocking);
        cudaStreamCreateWithFlags(&s2, cudaStreamNonBlocking);
        cudaEventCreateWithFlags(&evFork,   cudaEventDisableTiming);
        cudaEventCreateWithFlags(&evScores, cudaEventDisableTiming);
        cudaEventCreateWithFlags(&evGate,   cudaEventDisableTiming);
        cudaEventCreateWithFlags(&evPre,    cudaEventDisableTiming);
        cudaEventCreateWithFlags(&evP,      cudaEventDisableTiming);
        init_done = 1;
    }

    // fork: s1 carries prologue + edge chain; s2 computes p concurrently
    cudaEventRecord(evFork, 0);
    cudaStreamWaitEvent(s1, evFork, 0);

    k_pre2<<<ZB + 2, 256, 0, s1>>>((const long long*)ei, E, N, w_gcn, b_gcn, w_score, b_score, ZB);
    cudaEventRecord(evPre, s1);
    cudaStreamWaitEvent(s2, evPre, 0);
    k_p<<<PB, 256, 0, s2>>>(x, N);            // needs wv; concurrent with k_deg
    cudaEventRecord(evP, s2);

    k_deg<<<EB2, 256, 0, s1>>>(ei, E);
    cudaStreamWaitEvent(s1, evP, 0);          // dinv needs p + deg
    k_dinv<<<NB, 256, 0, s1>>>(N);
    k_edge<<<EB2, 256, 0, s1>>>(ei, E);
    k_scores<<<NB, 256, 0, s1>>>(N);
    cudaEventRecord(evScores, s1);
    k_gate<<<EB2, 256, 0, s1>>>(ei, ew, alpha, beta, out + (size_t)N * D, E);   // overlaps k_final3
    cudaEventRecord(evGate, s1);

    // s0 critical path
    k_zeroG<<<16, 256>>>();
    k_G<<<148, 512, SMG>>>(x, N, nChunks);
    k_power<<<PWB, 1024, SMP>>>(w_e1);

    cudaStreamWaitEvent(0, evScores, 0);
    k_final3<<<148, 512, SMF>>>(x, b_e1, b_e2, w_e1, w_e2, out, N, nChunks);
    cudaStreamWaitEvent(0, evGate, 0);   // join s1 fully for capture
}

// round 14
// speedup vs baseline: 1.2311x; 1.0990x over previous
#include <cuda_runtime.h>
#include <math.h>
#include <stdint.h>

#define D 128
#define PAD 132            // k_final/k_power smem row pitch (floats)
#define PADG 136           // k_G pitch: mod 32 == 8 -> conflict-free mma fragment loads
#define PADE 129
#define NMAX 65536
#define NSQ 10             // REQUIRED: lambda2/lambda1 ~ 0.996 (Tracy-Widom edge); NSQ=8 fails
#define NREF 5
#define PWB 32             // k_power blocks (4 rows each)

static __device__ int   g_degi[NMAX];
static __device__ float g_dinv[NMAX];
static __device__ float g_p[NMAX];
static __device__ float g_dp[NMAX];
static __device__ float g_sacc[NMAX];
static __device__ float g_scores[NMAX];
static __device__ __align__(16) float g_G[D * D];
static __device__ __align__(16) float g_Ea[D * D];
static __device__ __align__(16) float g_Eb[D * D];
static __device__ float g_v1[D];
static __device__ float g_a1[D];
static __device__ float g_wv[D];
static __device__ float g_bg;
static __device__ int   g_i32;
static __device__ int   g_bar;

// ---------------------------------------------------------------- utilities
__device__ __forceinline__ float sigmoidf_(float z) {
    return 1.0f / (1.0f + expf(-z));
}

__device__ __forceinline__ unsigned smem_u32(const void* p) {
    return (unsigned)__cvta_generic_to_shared(p);
}
__device__ __forceinline__ void cp16(unsigned s, const void* g) {
    asm volatile("cp.async.cg.shared.global [%0], [%1], 16;\n" :: "r"(s), "l"(g));
}
#define CP_COMMIT() asm volatile("cp.async.commit_group;\n" ::)
#define CP_WAIT(n)  asm volatile("cp.async.wait_group %0;\n" :: "n"(n))

__device__ __forceinline__ uint32_t tf32cvt(float f) {
    uint32_t u;
    asm("cvt.rna.tf32.f32 %0, %1;" : "=r"(u) : "f"(f));
    return u;
}

__device__ __forceinline__ void mma_tf32(float* c, uint32_t a0, uint32_t a1, uint32_t a2, uint32_t a3,
                                         uint32_t b0, uint32_t b1) {
    asm volatile("mma.sync.aligned.m16n8k8.row.col.f32.tf32.tf32.f32 "
                 "{%0,%1,%2,%3}, {%4,%5,%6,%7}, {%8,%9}, {%0,%1,%2,%3};"
                 : "+f"(c[0]), "+f"(c[1]), "+f"(c[2]), "+f"(c[3])
                 : "r"(a0), "r"(a1), "r"(a2), "r"(a3), "r"(b0), "r"(b1));
}

// L2-coherent float4 load for cross-block exchange in k_power.
__device__ __forceinline__ float4 ldcg4(const float4* p) {
    float4 v;
    asm volatile("ld.global.cg.v4.f32 {%0,%1,%2,%3}, [%4];"
                 : "=f"(v.x), "=f"(v.y), "=f"(v.z), "=f"(v.w) : "l"(p));
    return v;
}

// ---------------------------------------------------------------- s0 micro-prologue: zero g_G + g_bar
__global__ void k_zeroG() {
    int i = blockIdx.x * 256 + threadIdx.x;     // 16*256 = 4096 = D*D/4
    ((float4*)g_G)[i] = make_float4(0.f, 0.f, 0.f, 0.f);
    if (i == 0) g_bar = 0;
}

// ---------------------------------------------------------------- s1 prologue: zero degi + detect + wv/bg
__global__ void k_pre2(const long long* ei, int E, int N,
                       const float* __restrict__ wg, const float* __restrict__ bgc,
                       const float* __restrict__ ws, const float* __restrict__ bs, int ZB) {
    int b = blockIdx.x, t = threadIdx.x;
    if (b < ZB) {
        int i = b * 256 + t;
        if (i < N) g_degi[i] = 0;
    } else if (b == ZB) {
        __shared__ int flag;
        if (t == 0) flag = 0;
        __syncthreads();
        int n = E < 1024 ? E : 1024;
        for (int e = t; e < n; e += 256)
            if ((unsigned long long)ei[e] >= (unsigned long long)N) flag = 1;
        __syncthreads();
        if (t == 0) g_i32 = flag;
    } else {
        __shared__ float wss[D];
        if (t < D) wss[t] = ws[t];
        __syncthreads();
        if (t < D) {
            float s = 0.0f;
            #pragma unroll 8
            for (int m = 0; m < D; m++) s += wg[t * D + m] * wss[m];
            g_wv[t] = s;
        }
        if (t == 0) {
            float bsum = bs[0];
            for (int m = 0; m < D; m++) bsum += bgc[m] * wss[m];
            g_bg = bsum;
        }
    }
}

// ---------------------------------------------------------------- edge/score chain
__global__ void k_p(const float* __restrict__ x, int N) {
    int w = (blockIdx.x * blockDim.x + threadIdx.x) >> 5;
    int lane = threadIdx.x & 31;
    if (w >= N) return;
    float4 xv = ((const float4*)x)[(size_t)w * 32 + lane];
    float4 wv = *(const float4*)&g_wv[lane * 4];
    float s = xv.x * wv.x + xv.y * wv.y + xv.z * wv.z + xv.w * wv.w;
    #pragma unroll
    for (int o = 16; o; o >>= 1) s += __shfl_xor_sync(0xffffffffu, s, o);
    if (lane == 0) g_p[w] = s;
}

__global__ void k_deg(const void* ei, int E) {
    int e = (blockIdx.x * 256 + threadIdx.x) * 2;
    if (e >= E) return;
    if (g_i32) {
        const int* dst = (const int*)ei + E;
        atomicAdd(&g_degi[dst[e]], 1);
        if (e + 1 < E) atomicAdd(&g_degi[dst[e + 1]], 1);
    } else {
        const long long* dst = (const long long*)ei + E;
        if (e + 1 < E) {
            longlong2 d = *(const longlong2*)&dst[e];
            atomicAdd(&g_degi[(int)d.x], 1);
            atomicAdd(&g_degi[(int)d.y], 1);
        } else {
            atomicAdd(&g_degi[(int)dst[e]], 1);
        }
    }
}

// dinv, dp = dinv*p; sacc initialized with self-loop term dp[i]
__global__ void k_dinv(int N) {
    int i = blockIdx.x * 256 + threadIdx.x;
    if (i >= N) return;
    float di = rsqrtf((float)(g_degi[i] + 1));
    float dpv = di * g_p[i];
    g_dinv[i] = di;
    g_dp[i] = dpv;
    g_sacc[i] = dpv;
}

// sacc[t] += dp[s]  (one random gather per edge)
__global__ void k_edge(const void* ei, int E) {
    int e = (blockIdx.x * 256 + threadIdx.x) * 2;
    if (e >= E) return;
    if (g_i32) {
        const int* src = (const int*)ei;
        const int* dst = src + E;
        #pragma unroll
        for (int u = 0; u < 2; u++) {
            if (e + u >= E) break;
            atomicAdd(&g_sacc[dst[e + u]], g_dp[src[e + u]]);
        }
    } else {
        const long long* src = (const long long*)ei;
        const long long* dst = src + E;
        if (e + 1 < E) {
            longlong2 sv = *(const longlong2*)&src[e];
            longlong2 dv = *(const longlong2*)&dst[e];
            atomicAdd(&g_sacc[(int)dv.x], g_dp[(int)sv.x]);
            atomicAdd(&g_sacc[(int)dv.y], g_dp[(int)sv.y]);
        } else {
            atomicAdd(&g_sacc[(int)dst[e]], g_dp[(int)src[e]]);
        }
    }
}

__global__ void k_scores(int N) {
    int i = blockIdx.x * 256 + threadIdx.x;
    if (i >= N) return;
    g_scores[i] = sigmoidf_(g_dinv[i] * g_sacc[i] + g_bg);
}

__global__ void k_gate(const void* ei, const float* __restrict__ ew,
                       const float* __restrict__ al, const float* __restrict__ be,
                       float* __restrict__ out, int E) {
    int e = (blockIdx.x * 256 + threadIdx.x) * 2;
    if (e >= E) return;
    float a_ = al[0], b_ = be[0];
    if (g_i32) {
        const int* src = (const int*)ei;
        const int* dst = src + E;
        #pragma unroll
        for (int u = 0; u < 2; u++) {
            if (e + u >= E) break;
            int s = src[e + u], t = dst[e + u];
            float z = a_ * (g_scores[s] + g_scores[t]) + b_;
            out[e + u] = ew[e + u] * sigmoidf_(z);
        }
    } else {
        const long long* src = (const long long*)ei;
        const long long* dst = src + E;
        if (e + 1 < E) {
            longlong2 sv = *(const longlong2*)&src[e];
            longlong2 dv = *(const longlong2*)&dst[e];
            float2 w = *(const float2*)&ew[e];
            float z0 = a_ * (g_scores[(int)sv.x] + g_scores[(int)dv.x]) + b_;
            float z1 = a_ * (g_scores[(int)sv.y] + g_scores[(int)dv.y]) + b_;
            float2 o = make_float2(w.x * sigmoidf_(z0), w.y * sigmoidf_(z1));
            *(float2*)&out[e] = o;
        } else {
            int s = (int)src[e], t = (int)dst[e];
            float z = a_ * (g_scores[s] + g_scores[t]) + b_;
            out[e] = ew[e] * sigmoidf_(z);
        }
    }
}

// ---------------------------------------------------------------- Gram: tf32 mma, 3-pass hi/lo split
__global__ __launch_bounds__(512, 1) void k_G(const float* __restrict__ x, int N, int nChunks) {
    extern __shared__ float sm[];
    float* bufs[2] = { sm, sm + 128 * PADG };
    int tid = threadIdx.x;
    int wid = tid >> 5, lane = tid & 31;
    int wm = wid >> 2, wn = wid & 3;
    int gid = lane >> 2, tg = lane & 3;
    int m0 = wm * 32, n0 = wn * 32;
    int stride = gridDim.x;

    float acc[2][4][4];
    #pragma unroll
    for (int mi = 0; mi < 2; mi++)
        #pragma unroll
        for (int ni = 0; ni < 4; ni++)
            #pragma unroll
            for (int j = 0; j < 4; j++) acc[mi][ni][j] = 0.0f;

    int ch = blockIdx.x;
    if (ch < nChunks) {
        int R0 = ch * 128;
        if (R0 + 128 <= N) {
            #pragma unroll
            for (int u = 0; u < 8; u++) {
                int idx = tid + u * 512;
                int r = idx >> 5, c4 = idx & 31;
                cp16(smem_u32(&bufs[0][r * PADG + c4 * 4]), &x[((size_t)(R0 + r)) * 128 + c4 * 4]);
            }
        } else {
            #pragma unroll
            for (int u = 0; u < 8; u++) {
                int idx = tid + u * 512;
                int r = idx >> 5, c4 = idx & 31;
                int gr = R0 + r;
                float4 v = (gr < N) ? ((const float4*)x)[(size_t)gr * 32 + c4]
                                    : make_float4(0.f, 0.f, 0.f, 0.f);
                *(float4*)&bufs[0][r * PADG + c4 * 4] = v;
            }
        }
        CP_COMMIT();
    }

    int cur = 0;
    for (; ch < nChunks; ch += stride) {
        int nxt = ch + stride;
        if (nxt < nChunks) {
            float* bn = bufs[cur ^ 1];
            int R1 = nxt * 128;
            if (R1 + 128 <= N) {
                #pragma unroll
                for (int u = 0; u < 8; u++) {
                    int idx = tid + u * 512;
                    int r = idx >> 5, c4 = idx & 31;
                    cp16(smem_u32(&bn[r * PADG + c4 * 4]), &x[((size_t)(R1 + r)) * 128 + c4 * 4]);
                }
            } else {
                #pragma unroll
                for (int u = 0; u < 8; u++) {
                    int idx = tid + u * 512;
                    int r = idx >> 5, c4 = idx & 31;
                    int gr = R1 + r;
                    float4 v = (gr < N) ? ((const float4*)x)[(size_t)gr * 32 + c4]
                                        : make_float4(0.f, 0.f, 0.f, 0.f);
                    *(float4*)&bn[r * PADG + c4 * 4] = v;
                }
            }
            CP_COMMIT();
            CP_WAIT(1);
        } else {
            CP_WAIT(0);
        }
        __syncthreads();
        const float* bc = bufs[cur];

        #pragma unroll 2
        for (int ks = 0; ks < 16; ks++) {
            int k0 = ks * 8;
            uint32_t ah[2][4], al[2][4];
            #pragma unroll
            for (int mi = 0; mi < 2; mi++) {
                int i0 = m0 + mi * 16 + gid;
                float f0 = bc[(k0 + tg) * PADG + i0];
                float f1 = bc[(k0 + tg) * PADG + i0 + 8];
                float f2 = bc[(k0 + tg + 4) * PADG + i0];
                float f3 = bc[(k0 + tg + 4) * PADG + i0 + 8];
                ah[mi][0] = tf32cvt(f0); al[mi][0] = tf32cvt(f0 - __uint_as_float(ah[mi][0]));
                ah[mi][1] = tf32cvt(f1); al[mi][1] = tf32cvt(f1 - __uint_as_float(ah[mi][1]));
                ah[mi][2] = tf32cvt(f2); al[mi][2] = tf32cvt(f2 - __uint_as_float(ah[mi][2]));
                ah[mi][3] = tf32cvt(f3); al[mi][3] = tf32cvt(f3 - __uint_as_float(ah[mi][3]));
            }
            uint32_t bh[4][2], bl[4][2];
            #pragma unroll
            for (int ni = 0; ni < 4; ni++) {
                int j0 = n0 + ni * 8 + gid;
                float g0 = bc[(k0 + tg) * PADG + j0];
                float g1 = bc[(k0 + tg + 4) * PADG + j0];
                bh[ni][0] = tf32cvt(g0); bl[ni][0] = tf32cvt(g0 - __uint_as_float(bh[ni][0]));
                bh[ni][1] = tf32cvt(g1); bl[ni][1] = tf32cvt(g1 - __uint_as_float(bh[ni][1]));
            }
            #pragma unroll
            for (int mi = 0; mi < 2; mi++)
                #pragma unroll
                for (int ni = 0; ni < 4; ni++) {
                    mma_tf32(acc[mi][ni], ah[mi][0], ah[mi][1], ah[mi][2], ah[mi][3], bh[ni][0], bh[ni][1]);
                    mma_tf32(acc[mi][ni], ah[mi][0], ah[mi][1], ah[mi][2], ah[mi][3], bl[ni][0], bl[ni][1]);
                    mma_tf32(acc[mi][ni], al[mi][0], al[mi][1], al[mi][2], al[mi][3], bh[ni][0], bh[ni][1]);
                }
        }
        cur ^= 1;
        __syncthreads();
    }
    #pragma unroll
    for (int mi = 0; mi < 2; mi++)
        #pragma unroll
        for (int ni = 0; ni < 4; ni++) {
            int r = m0 + mi * 16 + gid, c = n0 + ni * 8 + 2 * tg;
            atomicAdd(&g_G[r * D + c],           acc[mi][ni][0]);
            atomicAdd(&g_G[r * D + c + 1],       acc[mi][ni][1]);
            atomicAdd(&g_G[(r + 8) * D + c],     acc[mi][ni][2]);
            atomicAdd(&g_G[(r + 8) * D + c + 1], acc[mi][ni][3]);
        }
}

// ---------------------------------------------------------------- fused power iteration + extract
// 32 blocks x 1024 threads; 4 rows/block (threads >= 512 only help load).
__global__ __launch_bounds__(1024, 1) void k_power(const float* __restrict__ w1) {
    extern __shared__ float sm[];
    float* As = sm;
    int tid = threadIdx.x;
    int wid = tid >> 5, lane = tid & 31;
    int r = blockIdx.x * 4 + (tid >> 7);   // valid when tid < 512
    int tx = tid & 127;
    __shared__ float redm[32];

    for (int it = 0; it < NSQ; it++) {
        const float* in = (it == 0) ? g_G : ((it & 1) ? g_Ea : g_Eb);
        float* outp = (it & 1) ? g_Eb : g_Ea;
        float m = 0.0f;
        #pragma unroll
        for (int u = 0; u < 4; u++) {
            int idx = tid + u * 1024;
            int rr = idx >> 5, c4 = idx & 31;
            float4 v = ldcg4(&((const float4*)in)[idx]);
            *(float4*)&As[rr * PAD + c4 * 4] = v;
            m = fmaxf(m, fmaxf(fmaxf(fabsf(v.x), fabsf(v.y)), fmaxf(fabsf(v.z), fabsf(v.w))));
        }
        #pragma unroll
        for (int o = 16; o; o >>= 1) m = fmaxf(m, __shfl_xor_sync(0xffffffffu, m, o));
        if (lane == 0) redm[wid] = m;
        __syncthreads();
        if (tid < 32) {
            float mm = redm[tid];
            #pragma unroll
            for (int o = 16; o; o >>= 1) mm = fmaxf(mm, __shfl_xor_sync(0xffffffffu, mm, o));
            if (tid == 0) redm[0] = mm;
        }
        __syncthreads();
        float inv = 1.0f / redm[0];
        float inv2 = inv * inv;

        if (tid < 512) {
            float acc = 0.0f;
            #pragma unroll 8
            for (int k = 0; k < D; k++) acc += As[r * PAD + k] * As[k * PAD + tx];
            outp[r * D + tx] = acc * inv2;
        }

        __threadfence();
        __syncthreads();
        if (tid == 0) {
            atomicAdd(&g_bar, 1);
            int target = PWB * (it + 1);
            while (*(volatile int*)&g_bar < target) { __nanosleep(64); }
            __threadfence();
        }
        __syncthreads();
    }

    if (blockIdx.x != 0) return;

    float* vv = sm + D * PADE;
    float* uu = vv + D;
    float* red = uu + D;
    __shared__ int redi[128];
    __shared__ int jm;
    const float* P = (NSQ & 1) ? g_Eb : g_Ea;
    for (int idx4 = tid; idx4 < D * D / 4; idx4 += 1024) {
        float4 v = ldcg4(&((const float4*)P)[idx4]);
        int idx = idx4 * 4;
        int rr = idx >> 7, c = idx & 127;
        As[rr * PADE + c + 0] = v.x;
        As[rr * PADE + c + 1] = v.y;
        As[rr * PADE + c + 2] = v.z;
        As[rr * PADE + c + 3] = v.w;
    }
    __syncthreads();
    if (tid < D) { red[tid] = As[tid * PADE + tid]; redi[tid] = tid; }
    __syncthreads();
    for (int s = 64; s > 0; s >>= 1) {
        if (tid < s && red[tid + s] > red[tid]) { red[tid] = red[tid + s]; redi[tid] = redi[tid + s]; }
        __syncthreads();
    }
    if (tid == 0) jm = redi[0];
    __syncthreads();
    if (tid < D) vv[tid] = As[jm * PADE + tid];
    __syncthreads();

    for (int itr = 0; itr < NREF; itr++) {
        if (tid < D) {
            float s = 0.0f;
            #pragma unroll 8
            for (int c = 0; c < D; c++) s += As[tid * PADE + c] * vv[c];
            uu[tid] = s;
            red[tid] = s * s;
        }
        __syncthreads();
        for (int r2 = 64; r2 > 0; r2 >>= 1) {
            if (tid < r2) red[tid] += red[tid + r2];
            __syncthreads();
        }
        float invn = rsqrtf(fmaxf(red[0], 1e-30f));
        __syncthreads();
        if (tid < D) vv[tid] = uu[tid] * invn;
        __syncthreads();
    }

    if (tid < D) {
        g_v1[tid] = vv[tid];
        float a = 0.0f;
        #pragma unroll 8
        for (int d2 = 0; d2 < D; d2++) a += vv[d2] * w1[d2 * D + tid];
        g_a1[tid] = a;
    }
}

// ---------------------------------------------------------------- fused enhancer, tf32 mma
__global__ __launch_bounds__(512, 1) void k_final3(const float* __restrict__ x,
                        const float* __restrict__ b1, const float* __restrict__ b2,
                        const float* __restrict__ w1, const float* __restrict__ w2,
                        float* __restrict__ out, int N, int nChunks) {
    extern __shared__ float sm[];
    float* xs  = sm;
    float* w1t = sm + 128 * PAD;
    float* w2t = w1t + 128 * PAD;
    float* q_s = w2t + 128 * PAD;
    float* sc_s = q_s + 128;
    __shared__ float v1_s[D], a1_s[D], be1_s[D], be2_s[D];

    int tid = threadIdx.x;
    int wid = tid >> 5, lane = tid & 31;
    int wm = wid >> 2, wn = wid & 3;
    int gid = lane >> 2, tg = lane & 3;
    int stride = gridDim.x;

    for (int idx = tid; idx < D * D; idx += 512) {
        int k = idx >> 7, n = idx & 127;
        w1t[n * PAD + k] = __uint_as_float(tf32cvt(w1[idx]));
        w2t[n * PAD + k] = __uint_as_float(tf32cvt(w2[idx]));
    }
    if (tid < D) {
        v1_s[tid] = g_v1[tid]; a1_s[tid] = g_a1[tid];
        be1_s[tid] = b1[tid];  be2_s[tid] = b2[tid];
    }

    float4 pf[8];
    int ch = blockIdx.x;
    if (ch < nChunks) {
        int R0 = ch * 128;
        #pragma unroll
        for (int u = 0; u < 8; u++) {
            int idx = tid + u * 512;
            int r = idx >> 5, c4 = idx & 31;
            int gr = R0 + r;
            pf[u] = (gr < N) ? ((const float4*)x)[(size_t)gr * 32 + c4]
                             : make_float4(0.f, 0.f, 0.f, 0.f);
        }
    }

    for (; ch < nChunks; ch += stride) {
        int R0 = ch * 128;
        __syncthreads();
        #pragma unroll
        for (int u = 0; u < 8; u++) {
            int idx = tid + u * 512;
            int r = idx >> 5, c4 = idx & 31;
            *(float4*)&xs[r * PAD + c4 * 4] = pf[u];
        }
        if (tid < 128) sc_s[tid] = (R0 + tid < N) ? g_scores[R0 + tid] : 0.0f;
        __syncthreads();
        if (tid < 128) {
            float q = 0.0f;
            #pragma unroll 8
            for (int d = 0; d < D; d++) q += xs[tid * PAD + d] * v1_s[d];
            q_s[tid] = q;
        }
        int nxt = ch + stride;
        if (nxt < nChunks) {
            int R1 = nxt * 128;
            #pragma unroll
            for (int u = 0; u < 8; u++) {
                int idx = tid + u * 512;
                int r = idx >> 5, c4 = idx & 31;
                int gr = R1 + r;
                pf[u] = (gr < N) ? ((const float4*)x)[(size_t)gr * 32 + c4]
                                 : make_float4(0.f, 0.f, 0.f, 0.f);
            }
        }
        __syncthreads();

        // GEMM1: z = x @ W1 (single-pass tf32)
        float cfr[2][4][4];
        #pragma unroll
        for (int mi = 0; mi < 2; mi++)
            #pragma unroll
            for (int ni = 0; ni < 4; ni++)
                #pragma unroll
                for (int j = 0; j < 4; j++) cfr[mi][ni][j] = 0.0f;

        #pragma unroll 2
        for (int ks = 0; ks < 16; ks++) {
            int k0 = ks * 8;
            uint32_t ah[2][4];
            #pragma unroll
            for (int mi = 0; mi < 2; mi++) {
                int r = wm * 32 + mi * 16 + gid;
                ah[mi][0] = tf32cvt(xs[r * PAD + k0 + tg]);
                ah[mi][1] = tf32cvt(xs[(r + 8) * PAD + k0 + tg]);
                ah[mi][2] = tf32cvt(xs[r * PAD + k0 + tg + 4]);
                ah[mi][3] = tf32cvt(xs[(r + 8) * PAD + k0 + tg + 4]);
            }
            uint32_t bh[4][2];
            #pragma unroll
            for (int ni = 0; ni < 4; ni++) {
                int c = wn * 32 + ni * 8 + gid;
                bh[ni][0] = __float_as_uint(w1t[c * PAD + k0 + tg]);
                bh[ni][1] = __float_as_uint(w1t[c * PAD + k0 + tg + 4]);
            }
            #pragma unroll
            for (int mi = 0; mi < 2; mi++)
                #pragma unroll
                for (int ni = 0; ni < 4; ni++)
                    mma_tf32(cfr[mi][ni], ah[mi][0], ah[mi][1], ah[mi][2], ah[mi][3], bh[ni][0], bh[ni][1]);
        }
        __syncthreads();

        // epilogue1: save residual x (thread-local read-before-write), relu, store PRE-ROUNDED tf32
        float xv_keep[2][4][4];
        #pragma unroll
        for (int mi = 0; mi < 2; mi++) {
            int r = wm * 32 + mi * 16 + gid;
            float qh0 = 0.5f * q_s[r], qh8 = 0.5f * q_s[r + 8];
            #pragma unroll
            for (int ni = 0; ni < 4; ni++) {
                int c = wn * 32 + ni * 8 + 2 * tg;
                float2 xo0 = *(const float2*)&xs[r * PAD + c];
                float2 xo1 = *(const float2*)&xs[(r + 8) * PAD + c];
                xv_keep[mi][ni][0] = xo0.x; xv_keep[mi][ni][1] = xo0.y;
                xv_keep[mi][ni][2] = xo1.x; xv_keep[mi][ni][3] = xo1.y;
                float z00 = 0.5f * cfr[mi][ni][0] + qh0 * a1_s[c]     + be1_s[c];
                float z01 = 0.5f * cfr[mi][ni][1] + qh0 * a1_s[c + 1] + be1_s[c + 1];
                float z10 = 0.5f * cfr[mi][ni][2] + qh8 * a1_s[c]     + be1_s[c];
                float z11 = 0.5f * cfr[mi][ni][3] + qh8 * a1_s[c + 1] + be1_s[c + 1];
                float2 p0 = make_float2(__uint_as_float(tf32cvt(fmaxf(z00, 0.f))),
                                        __uint_as_float(tf32cvt(fmaxf(z01, 0.f))));
                float2 p1 = make_float2(__uint_as_float(tf32cvt(fmaxf(z10, 0.f))),
                                        __uint_as_float(tf32cvt(fmaxf(z11, 0.f))));
                *(float2*)&xs[r * PAD + c]       = p0;
                *(float2*)&xs[(r + 8) * PAD + c] = p1;
            }
        }
        __syncthreads();

        // GEMM2: single pass, A pre-rounded
        #pragma unroll
        for (int mi = 0; mi < 2; mi++)
            #pragma unroll
            for (int ni = 0; ni < 4; ni++)
                #pragma unroll
                for (int j = 0; j < 4; j++) cfr[mi][ni][j] = 0.0f;

        #pragma unroll 2
        for (int ks = 0; ks < 16; ks++) {
            int k0 = ks * 8;
            uint32_t a2[2][4];
            #pragma unroll
            for (int mi = 0; mi < 2; mi++) {
                int r = wm * 32 + mi * 16 + gid;
                a2[mi][0] = __float_as_uint(xs[r * PAD + k0 + tg]);
                a2[mi][1] = __float_as_uint(xs[(r + 8) * PAD + k0 + tg]);
                a2[mi][2] = __float_as_uint(xs[r * PAD + k0 + tg + 4]);
                a2[mi][3] = __float_as_uint(xs[(r + 8) * PAD + k0 + tg + 4]);
            }
            uint32_t bh[4][2];
            #pragma unroll
            for (int ni = 0; ni < 4; ni++) {
                int c = wn * 32 + ni * 8 + gid;
                bh[ni][0] = __float_as_uint(w2t[c * PAD + k0 + tg]);
                bh[ni][1] = __float_as_uint(w2t[c * PAD + k0 + tg + 4]);
            }
            #pragma unroll
            for (int mi = 0; mi < 2; mi++)
                #pragma unroll
                for (int ni = 0; ni < 4; ni++)
                    mma_tf32(cfr[mi][ni], a2[mi][0], a2[mi][1], a2[mi][2], a2[mi][3], bh[ni][0], bh[ni][1]);
        }

        // epilogue2: residual from registers (no x re-read)
        #pragma unroll
        for (int mi = 0; mi < 2; mi++) {
            int r = wm * 32 + mi * 16 + gid;
            #pragma unroll
            for (int rr = 0; rr < 2; rr++) {
                int row = r + rr * 8;
                int gr = R0 + row;
                if (gr >= N) continue;
                float sc = sc_s[row], qh = 0.5f * q_s[row];
                #pragma unroll
                for (int ni = 0; ni < 4; ni++) {
                    int c = wn * 32 + ni * 8 + 2 * tg;
                    float e0 = cfr[mi][ni][rr * 2 + 0];
                    float e1 = cfr[mi][ni][rr * 2 + 1];
                    float o0 = (e0 + be2_s[c])     * sc + 0.5f * xv_keep[mi][ni][rr * 2 + 0] + qh * v1_s[c];
                    float o1 = (e1 + be2_s[c + 1]) * sc + 0.5f * xv_keep[mi][ni][rr * 2 + 1] + qh * v1_s[c + 1];
                    ((float2*)out)[(size_t)gr * 64 + (c >> 1)] = make_float2(o0, o1);
                }
            }
        }
    }
}

// ---------------------------------------------------------------- launch
extern "C" void kernel_launch(void* const* d_in, const int* in_sizes, int n_in,
                              void* d_out, int out_size) {
    const float* x       = (const float*)d_in[0];
    const void*  ei      = d_in[1];
    const float* ew      = (const float*)d_in[2];
    const float* w_gcn   = (const float*)d_in[3];
    const float* b_gcn   = (const float*)d_in[4];
    const float* w_score = (const float*)d_in[5];
    const float* b_score = (const float*)d_in[6];
    const float* alpha   = (const float*)d_in[7];
    const float* beta    = (const float*)d_in[8];
    const float* w_e1    = (const float*)d_in[9];
    const float* b_e1    = (const float*)d_in[10];
    const float* w_e2    = (const float*)d_in[11];
    const float* b_e2    = (const float*)d_in[12];
    float* out = (float*)d_out;

    int N = in_sizes[0] / D;
    int E = in_sizes[2];
    int nChunks = (N + 127) / 128;
    int NB = (N + 255) / 256;
    int E2 = (E + 1) / 2;
    int EB2 = (E2 + 255) / 256;
    int ZB = (N + 255) / 256;
    int PB = (N * 32 + 255) / 256;

    const int SMG = 2 * 128 * PADG * 4;
    const int SMF = (3 * 128 * PAD + 256) * 4;
    const int SMP = (128 * PAD) * 4;

    static int init_done = 0;
    static cudaStream_t s1, s2;
    static cudaEvent_t evFork, evScores, evGate, evPre, evP;
    if (!init_done) {
        cudaFuncSetAttribute(k_G,      cudaFuncAttributeMaxDynamicSharedMemorySize, SMG);
        cudaFuncSetAttribute(k_power,  cudaFuncAttributeMaxDynamicSharedMemorySize, SMP);
        cudaFuncSetAttribute(k_final3, cudaFuncAttributeMaxDynamicSharedMemorySize, SMF);
        cudaStreamCreateWithFlags(&s1, cudaStreamNonBlocking);
        cudaStreamCreateWithFlags(&s2, cudaStreamNonBlocking);
        cudaEventCreateWithFlags(&evFork,   cudaEventDisableTiming);
        cudaEventCreateWithFlags(&evScores, cudaEventDisableTiming);
        cudaEventCreateWithFlags(&evGate,   cudaEventDisableTiming);
        cudaEventCreateWithFlags(&evPre,    cudaEventDisableTiming);
        cudaEventCreateWithFlags(&evP,      cudaEventDisableTiming);
        init_done = 1;
    }

    // fork: s1 carries prologue + edge chain; s2 computes p concurrently
    cudaEventRecord(evFork, 0);
    cudaStreamWaitEvent(s1, evFork, 0);

    k_pre2<<<ZB + 2, 256, 0, s1>>>((const long long*)ei, E, N, w_gcn, b_gcn, w_score, b_score, ZB);
    cudaEventRecord(evPre, s1);
    cudaStreamWaitEvent(s2, evPre, 0);
    k_p<<<PB, 256, 0, s2>>>(x, N);            // needs wv; concurrent with k_deg
    cudaEventRecord(evP, s2);

    k_deg<<<EB2, 256, 0, s1>>>(ei, E);
    cudaStreamWaitEvent(s1, evP, 0);          // dinv needs p + deg
    k_dinv<<<NB, 256, 0, s1>>>(N);
    k_edge<<<EB2, 256, 0, s1>>>(ei, E);
    k_scores<<<NB, 256, 0, s1>>>(N);
    cudaEventRecord(evScores, s1);
    k_gate<<<EB2, 256, 0, s1>>>(ei, ew, alpha, beta, out + (size_t)N * D, E);   // overlaps k_final3
    cudaEventRecord(evGate, s1);

    // s0 critical path
    k_zeroG<<<16, 256>>>();
    k_G<<<148, 512, SMG>>>(x, N, nChunks);
    k_power<<<PWB, 1024, SMP>>>(w_e1);

    cudaStreamWaitEvent(0, evScores, 0);
    k_final3<<<148, 512, SMF>>>(x, b_e1, b_e2, w_e1, w_e2, out, N, nChunks);
    cudaStreamWaitEvent(0, evGate, 0);   // join s1 fully for capture
}

// round 16
// speedup vs baseline: 1.3007x; 1.0566x over previous
#include <cuda_runtime.h>
#include <math.h>
#include <stdint.h>

#define D 128
#define PAD 132            // k_final/k_power smem row pitch (floats)
#define PADG 136           // k_G pitch: mod 32 == 8 -> conflict-free mma fragment loads
#define PADE 129
#define NMAX 65536
#define NSQ 9              // effective exponent 256 (extract reads it=NSQ-2 buffer).
                           // Calibrated: R13 (E=128) measured c*w=1.8e-3 -> E=256 <= 3.2e-4. Do NOT lower.
#define NREF 5
#define PWB 32             // k_power blocks (4 rows each)

static __device__ int   g_degi[NMAX];
static __device__ float g_dinv[NMAX];
static __device__ float g_p[NMAX];
static __device__ float g_dp[NMAX];
static __device__ float g_sacc[NMAX];
static __device__ float g_scores[NMAX];
static __device__ __align__(16) float g_G[D * D];
static __device__ __align__(16) float g_Ea[D * D];
static __device__ __align__(16) float g_Eb[D * D];
static __device__ float g_v1[D];
static __device__ float g_a1[D];
static __device__ float g_wv[D];
static __device__ float g_bg;
static __device__ int   g_i32;
static __device__ int   g_bar;

// ---------------------------------------------------------------- utilities
__device__ __forceinline__ float sigmoidf_(float z) {
    return 1.0f / (1.0f + expf(-z));
}

__device__ __forceinline__ unsigned smem_u32(const void* p) {
    return (unsigned)__cvta_generic_to_shared(p);
}
__device__ __forceinline__ void cp16(unsigned s, const void* g) {
    asm volatile("cp.async.cg.shared.global [%0], [%1], 16;\n" :: "r"(s), "l"(g));
}
#define CP_COMMIT() asm volatile("cp.async.commit_group;\n" ::)
#define CP_WAIT(n)  asm volatile("cp.async.wait_group %0;\n" :: "n"(n))

__device__ __forceinline__ uint32_t tf32cvt(float f) {
    uint32_t u;
    asm("cvt.rna.tf32.f32 %0, %1;" : "=r"(u) : "f"(f));
    return u;
}

__device__ __forceinline__ void mma_tf32(float* c, uint32_t a0, uint32_t a1, uint32_t a2, uint32_t a3,
                                         uint32_t b0, uint32_t b1) {
    asm volatile("mma.sync.aligned.m16n8k8.row.col.f32.tf32.tf32.f32 "
                 "{%0,%1,%2,%3}, {%4,%5,%6,%7}, {%8,%9}, {%0,%1,%2,%3};"
                 : "+f"(c[0]), "+f"(c[1]), "+f"(c[2]), "+f"(c[3])
                 : "r"(a0), "r"(a1), "r"(a2), "r"(a3), "r"(b0), "r"(b1));
}

// L2-coherent float4 load for cross-block exchange in k_power.
__device__ __forceinline__ float4 ldcg4(const float4* p) {
    float4 v;
    asm volatile("ld.global.cg.v4.f32 {%0,%1,%2,%3}, [%4];"
                 : "=f"(v.x), "=f"(v.y), "=f"(v.z), "=f"(v.w) : "l"(p));
    return v;
}

// ---------------------------------------------------------------- s0 prologue: zero g_G + g_bar + g_degi
__global__ void k_zeroAll(int N) {
    int i = blockIdx.x * 256 + threadIdx.x;
    if (i < N) g_degi[i] = 0;
    if (i < D * D / 4) ((float4*)g_G)[i] = make_float4(0.f, 0.f, 0.f, 0.f);
    if (i == 0) g_bar = 0;
}

// ---------------------------------------------------------------- s1 prologue: detect + wv/bg (2 blocks)
__global__ void k_pre3(const long long* ei, int E, int N,
                       const float* __restrict__ wg, const float* __restrict__ bgc,
                       const float* __restrict__ ws, const float* __restrict__ bs) {
    int t = threadIdx.x;
    if (blockIdx.x == 0) {
        __shared__ int flag;
        if (t == 0) flag = 0;
        __syncthreads();
        int n = E < 1024 ? E : 1024;
        for (int e = t; e < n; e += 256)
            if ((unsigned long long)ei[e] >= (unsigned long long)N) flag = 1;
        __syncthreads();
        if (t == 0) g_i32 = flag;
    } else {
        __shared__ float wss[D];
        if (t < D) wss[t] = ws[t];
        __syncthreads();
        if (t < D) {
            float s = 0.0f;
            #pragma unroll 8
            for (int m = 0; m < D; m++) s += wg[t * D + m] * wss[m];
            g_wv[t] = s;
        }
        if (t == 0) {
            float bsum = bs[0];
            for (int m = 0; m < D; m++) bsum += bgc[m] * wss[m];
            g_bg = bsum;
        }
    }
}

// ---------------------------------------------------------------- edge/score chain
__global__ void k_p(const float* __restrict__ x, int N) {
    int w = (blockIdx.x * blockDim.x + threadIdx.x) >> 5;
    int lane = threadIdx.x & 31;
    if (w >= N) return;
    float4 xv = ((const float4*)x)[(size_t)w * 32 + lane];
    float4 wv = *(const float4*)&g_wv[lane * 4];
    float s = xv.x * wv.x + xv.y * wv.y + xv.z * wv.z + xv.w * wv.w;
    #pragma unroll
    for (int o = 16; o; o >>= 1) s += __shfl_xor_sync(0xffffffffu, s, o);
    if (lane == 0) g_p[w] = s;
}

__global__ void k_deg(const void* ei, int E) {
    int e = (blockIdx.x * 256 + threadIdx.x) * 2;
    if (e >= E) return;
    if (g_i32) {
        const int* dst = (const int*)ei + E;
        atomicAdd(&g_degi[dst[e]], 1);
        if (e + 1 < E) atomicAdd(&g_degi[dst[e + 1]], 1);
    } else {
        const long long* dst = (const long long*)ei + E;
        if (e + 1 < E) {
            longlong2 d = *(const longlong2*)&dst[e];
            atomicAdd(&g_degi[(int)d.x], 1);
            atomicAdd(&g_degi[(int)d.y], 1);
        } else {
            atomicAdd(&g_degi[(int)dst[e]], 1);
        }
    }
}

// dinv, dp = dinv*p; sacc initialized with self-loop term dp[i]
__global__ void k_dinv(int N) {
    int i = blockIdx.x * 256 + threadIdx.x;
    if (i >= N) return;
    float di = rsqrtf((float)(g_degi[i] + 1));
    float dpv = di * g_p[i];
    g_dinv[i] = di;
    g_dp[i] = dpv;
    g_sacc[i] = dpv;
}

// sacc[t] += dp[s]  (one random gather per edge)
__global__ void k_edge(const void* ei, int E) {
    int e = (blockIdx.x * 256 + threadIdx.x) * 2;
    if (e >= E) return;
    if (g_i32) {
        const int* src = (const int*)ei;
        const int* dst = src + E;
        #pragma unroll
        for (int u = 0; u < 2; u++) {
            if (e + u >= E) break;
            atomicAdd(&g_sacc[dst[e + u]], g_dp[src[e + u]]);
        }
    } else {
        const long long* src = (const long long*)ei;
        const long long* dst = src + E;
        if (e + 1 < E) {
            longlong2 sv = *(const longlong2*)&src[e];
            longlong2 dv = *(const longlong2*)&dst[e];
            atomicAdd(&g_sacc[(int)dv.x], g_dp[(int)sv.x]);
            atomicAdd(&g_sacc[(int)dv.y], g_dp[(int)sv.y]);
        } else {
            atomicAdd(&g_sacc[(int)dst[e]], g_dp[(int)src[e]]);
        }
    }
}

__global__ void k_scores(int N) {
    int i = blockIdx.x * 256 + threadIdx.x;
    if (i >= N) return;
    g_scores[i] = sigmoidf_(g_dinv[i] * g_sacc[i] + g_bg);
}

__global__ void k_gate(const void* ei, const float* __restrict__ ew,
                       const float* __restrict__ al, const float* __restrict__ be,
                       float* __restrict__ out, int E) {
    int e = (blockIdx.x * 256 + threadIdx.x) * 2;
    if (e >= E) return;
    float a_ = al[0], b_ = be[0];
    if (g_i32) {
        const int* src = (const int*)ei;
        const int* dst = src + E;
        #pragma unroll
        for (int u = 0; u < 2; u++) {
            if (e + u >= E) break;
            int s = src[e + u], t = dst[e + u];
            float z = a_ * (g_scores[s] + g_scores[t]) + b_;
            out[e + u] = ew[e + u] * sigmoidf_(z);
        }
    } else {
        const long long* src = (const long long*)ei;
        const long long* dst = src + E;
        if (e + 1 < E) {
            longlong2 sv = *(const longlong2*)&src[e];
            longlong2 dv = *(const longlong2*)&dst[e];
            float2 w = *(const float2*)&ew[e];
            float z0 = a_ * (g_scores[(int)sv.x] + g_scores[(int)dv.x]) + b_;
            float z1 = a_ * (g_scores[(int)sv.y] + g_scores[(int)dv.y]) + b_;
            float2 o = make_float2(w.x * sigmoidf_(z0), w.y * sigmoidf_(z1));
            *(float2*)&out[e] = o;
        } else {
            int s = (int)src[e], t = (int)dst[e];
            float z = a_ * (g_scores[s] + g_scores[t]) + b_;
            out[e] = ew[e] * sigmoidf_(z);
        }
    }
}

// ---------------------------------------------------------------- Gram: tf32 mma, 3-pass hi/lo split
// (3-pass REQUIRED: eigengap ~0.005 amplifies any dG by ~200x into v1)
__global__ __launch_bounds__(512, 1) void k_G(const float* __restrict__ x, int N, int nChunks) {
    extern __shared__ float sm[];
    float* bufs[2] = { sm, sm + 128 * PADG };
    int tid = threadIdx.x;
    int wid = tid >> 5, lane = tid & 31;
    int wm = wid >> 2, wn = wid & 3;
    int gid = lane >> 2, tg = lane & 3;
    int m0 = wm * 32, n0 = wn * 32;
    int stride = gridDim.x;

    float acc[2][4][4];
    #pragma unroll
    for (int mi = 0; mi < 2; mi++)
        #pragma unroll
        for (int ni = 0; ni < 4; ni++)
            #pragma unroll
            for (int j = 0; j < 4; j++) acc[mi][ni][j] = 0.0f;

    int ch = blockIdx.x;
    if (ch < nChunks) {
        int R0 = ch * 128;
        if (R0 + 128 <= N) {
            #pragma unroll
            for (int u = 0; u < 8; u++) {
                int idx = tid + u * 512;
                int r = idx >> 5, c4 = idx & 31;
                cp16(smem_u32(&bufs[0][r * PADG + c4 * 4]), &x[((size_t)(R0 + r)) * 128 + c4 * 4]);
            }
        } else {
            #pragma unroll
            for (int u = 0; u < 8; u++) {
                int idx = tid + u * 512;
                int r = idx >> 5, c4 = idx & 31;
                int gr = R0 + r;
                float4 v = (gr < N) ? ((const float4*)x)[(size_t)gr * 32 + c4]
                                    : make_float4(0.f, 0.f, 0.f, 0.f);
                *(float4*)&bufs[0][r * PADG + c4 * 4] = v;
            }
        }
        CP_COMMIT();
    }

    int cur = 0;
    for (; ch < nChunks; ch += stride) {
        int nxt = ch + stride;
        if (nxt < nChunks) {
            float* bn = bufs[cur ^ 1];
            int R1 = nxt * 128;
            if (R1 + 128 <= N) {
                #pragma unroll
                for (int u = 0; u < 8; u++) {
                    int idx = tid + u * 512;
                    int r = idx >> 5, c4 = idx & 31;
                    cp16(smem_u32(&bn[r * PADG + c4 * 4]), &x[((size_t)(R1 + r)) * 128 + c4 * 4]);
                }
            } else {
                #pragma unroll
                for (int u = 0; u < 8; u++) {
                    int idx = tid + u * 512;
                    int r = idx >> 5, c4 = idx & 31;
                    int gr = R1 + r;
                    float4 v = (gr < N) ? ((const float4*)x)[(size_t)gr * 32 + c4]
                                        : make_float4(0.f, 0.f, 0.f, 0.f);
                    *(float4*)&bn[r * PADG + c4 * 4] = v;
                }
            }
            CP_COMMIT();
            CP_WAIT(1);
        } else {
            CP_WAIT(0);
        }
        __syncthreads();
        const float* bc = bufs[cur];

        #pragma unroll 2
        for (int ks = 0; ks < 16; ks++) {
            int k0 = ks * 8;
            uint32_t ah[2][4], al[2][4];
            #pragma unroll
            for (int mi = 0; mi < 2; mi++) {
                int i0 = m0 + mi * 16 + gid;
                float f0 = bc[(k0 + tg) * PADG + i0];
                float f1 = bc[(k0 + tg) * PADG + i0 + 8];
                float f2 = bc[(k0 + tg + 4) * PADG + i0];
                float f3 = bc[(k0 + tg + 4) * PADG + i0 + 8];
                ah[mi][0] = tf32cvt(f0); al[mi][0] = tf32cvt(f0 - __uint_as_float(ah[mi][0]));
                ah[mi][1] = tf32cvt(f1); al[mi][1] = tf32cvt(f1 - __uint_as_float(ah[mi][1]));
                ah[mi][2] = tf32cvt(f2); al[mi][2] = tf32cvt(f2 - __uint_as_float(ah[mi][2]));
                ah[mi][3] = tf32cvt(f3); al[mi][3] = tf32cvt(f3 - __uint_as_float(ah[mi][3]));
            }
            uint32_t bh[4][2], bl[4][2];
            #pragma unroll
            for (int ni = 0; ni < 4; ni++) {
                int j0 = n0 + ni * 8 + gid;
                float g0 = bc[(k0 + tg) * PADG + j0];
                float g1 = bc[(k0 + tg + 4) * PADG + j0];
                bh[ni][0] = tf32cvt(g0); bl[ni][0] = tf32cvt(g0 - __uint_as_float(bh[ni][0]));
                bh[ni][1] = tf32cvt(g1); bl[ni][1] = tf32cvt(g1 - __uint_as_float(bh[ni][1]));
            }
            #pragma unroll
            for (int mi = 0; mi < 2; mi++)
                #pragma unroll
                for (int ni = 0; ni < 4; ni++) {
                    mma_tf32(acc[mi][ni], ah[mi][0], ah[mi][1], ah[mi][2], ah[mi][3], bh[ni][0], bh[ni][1]);
                    mma_tf32(acc[mi][ni], ah[mi][0], ah[mi][1], ah[mi][2], ah[mi][3], bl[ni][0], bl[ni][1]);
                    mma_tf32(acc[mi][ni], al[mi][0], al[mi][1], al[mi][2], al[mi][3], bh[ni][0], bh[ni][1]);
                }
        }
        cur ^= 1;
        __syncthreads();
    }
    #pragma unroll
    for (int mi = 0; mi < 2; mi++)
        #pragma unroll
        for (int ni = 0; ni < 4; ni++) {
            int r = m0 + mi * 16 + gid, c = n0 + ni * 8 + 2 * tg;
            atomicAdd(&g_G[r * D + c],           acc[mi][ni][0]);
            atomicAdd(&g_G[r * D + c + 1],       acc[mi][ni][1]);
            atomicAdd(&g_G[(r + 8) * D + c],     acc[mi][ni][2]);
            atomicAdd(&g_G[(r + 8) * D + c + 1], acc[mi][ni][3]);
        }
}

// ---------------------------------------------------------------- fused power iteration + extract
__global__ __launch_bounds__(1024, 1) void k_power(const float* __restrict__ w1) {
    extern __shared__ float sm[];
    float* As = sm;
    int tid = threadIdx.x;
    int wid = tid >> 5, lane = tid & 31;
    int r = blockIdx.x * 4 + (tid >> 7);   // valid when tid < 512
    int tx = tid & 127;
    __shared__ float redm[32];

    for (int it = 0; it < NSQ; it++) {
        const float* in = (it == 0) ? g_G : ((it & 1) ? g_Ea : g_Eb);
        float* outp = (it & 1) ? g_Eb : g_Ea;
        float m = 0.0f;
        #pragma unroll
        for (int u = 0; u < 4; u++) {
            int idx = tid + u * 1024;
            int rr = idx >> 5, c4 = idx & 31;
            float4 v = ldcg4(&((const float4*)in)[idx]);
            *(float4*)&As[rr * PAD + c4 * 4] = v;
            m = fmaxf(m, fmaxf(fmaxf(fabsf(v.x), fabsf(v.y)), fmaxf(fabsf(v.z), fabsf(v.w))));
        }
        #pragma unroll
        for (int o = 16; o; o >>= 1) m = fmaxf(m, __shfl_xor_sync(0xffffffffu, m, o));
        if (lane == 0) redm[wid] = m;
        __syncthreads();
        if (tid < 32) {
            float mm = redm[tid];
            #pragma unroll
            for (int o = 16; o; o >>= 1) mm = fmaxf(mm, __shfl_xor_sync(0xffffffffu, mm, o));
            if (tid == 0) redm[0] = mm;
        }
        __syncthreads();
        float inv = 1.0f / redm[0];
        float inv2 = inv * inv;

        if (tid < 512) {
            float acc = 0.0f;
            #pragma unroll 8
            for (int k = 0; k < D; k++) acc += As[r * PAD + k] * As[k * PAD + tx];
            outp[r * D + tx] = acc * inv2;
        }

        __threadfence();
        __syncthreads();
        if (tid == 0) {
            atomicAdd(&g_bar, 1);
            int target = PWB * (it + 1);
            while (*(volatile int*)&g_bar < target) { __nanosleep(64); }
            __threadfence();
        }
        __syncthreads();
    }

    if (blockIdx.x != 0) return;

    float* vv = sm + D * PADE;
    float* uu = vv + D;
    float* red = uu + D;
    __shared__ int redi[128];
    __shared__ int jm;
    const float* P = (NSQ & 1) ? g_Eb : g_Ea;   // buffer from it = NSQ-2 (established semantics)
    for (int idx4 = tid; idx4 < D * D / 4; idx4 += 1024) {
        float4 v = ldcg4(&((const float4*)P)[idx4]);
        int idx = idx4 * 4;
        int rr = idx >> 7, c = idx & 127;
        As[rr * PADE + c + 0] = v.x;
        As[rr * PADE + c + 1] = v.y;
        As[rr * PADE + c + 2] = v.z;
        As[rr * PADE + c + 3] = v.w;
    }
    __syncthreads();
    if (tid < D) { red[tid] = As[tid * PADE + tid]; redi[tid] = tid; }
    __syncthreads();
    for (int s = 64; s > 0; s >>= 1) {
        if (tid < s && red[tid + s] > red[tid]) { red[tid] = red[tid + s]; redi[tid] = redi[tid + s]; }
        __syncthreads();
    }
    if (tid == 0) jm = redi[0];
    __syncthreads();
    if (tid < D) vv[tid] = As[jm * PADE + tid];
    __syncthreads();

    for (int itr = 0; itr < NREF; itr++) {
        if (tid < D) {
            float s = 0.0f;
            #pragma unroll 8
            for (int c = 0; c < D; c++) s += As[tid * PADE + c] * vv[c];
            uu[tid] = s;
            red[tid] = s * s;
        }
        __syncthreads();
        for (int r2 = 64; r2 > 0; r2 >>= 1) {
            if (tid < r2) red[tid] += red[tid + r2];
            __syncthreads();
        }
        float invn = rsqrtf(fmaxf(red[0], 1e-30f));
        __syncthreads();
        if (tid < D) vv[tid] = uu[tid] * invn;
        __syncthreads();
    }

    if (tid < D) {
        g_v1[tid] = vv[tid];
        float a = 0.0f;
        #pragma unroll 8
        for (int d2 = 0; d2 < D; d2++) a += vv[d2] * w1[d2 * D + tid];
        g_a1[tid] = a;
    }
}

// ---------------------------------------------------------------- fused enhancer, tf32 mma
__global__ __launch_bounds__(512, 1) void k_final3(const float* __restrict__ x,
                        const float* __restrict__ b1, const float* __restrict__ b2,
                        const float* __restrict__ w1, const float* __restrict__ w2,
                        float* __restrict__ out, int N, int nChunks) {
    extern __shared__ float sm[];
    float* xs  = sm;
    float* w1t = sm + 128 * PAD;
    float* w2t = w1t + 128 * PAD;
    float* q_s = w2t + 128 * PAD;
    float* sc_s = q_s + 128;
    __shared__ float v1_s[D], a1_s[D], be1_s[D], be2_s[D];

    int tid = threadIdx.x;
    int wid = tid >> 5, lane = tid & 31;
    int wm = wid >> 2, wn = wid & 3;
    int gid = lane >> 2, tg = lane & 3;
    int stride = gridDim.x;

    for (int idx = tid; idx < D * D; idx += 512) {
        int k = idx >> 7, n = idx & 127;
        w1t[n * PAD + k] = __uint_as_float(tf32cvt(w1[idx]));
        w2t[n * PAD + k] = __uint_as_float(tf32cvt(w2[idx]));
    }
    if (tid < D) {
        v1_s[tid] = g_v1[tid]; a1_s[tid] = g_a1[tid];
        be1_s[tid] = b1[tid];  be2_s[tid] = b2[tid];
    }

    float4 pf[8];
    int ch = blockIdx.x;
    if (ch < nChunks) {
        int R0 = ch * 128;
        #pragma unroll
        for (int u = 0; u < 8; u++) {
            int idx = tid + u * 512;
            int r = idx >> 5, c4 = idx & 31;
            int gr = R0 + r;
            pf[u] = (gr < N) ? ((const float4*)x)[(size_t)gr * 32 + c4]
                             : make_float4(0.f, 0.f, 0.f, 0.f);
        }
    }

    for (; ch < nChunks; ch += stride) {
        int R0 = ch * 128;
        __syncthreads();
        #pragma unroll
        for (int u = 0; u < 8; u++) {
            int idx = tid + u * 512;
            int r = idx >> 5, c4 = idx & 31;
            *(float4*)&xs[r * PAD + c4 * 4] = pf[u];
        }
        if (tid < 128) sc_s[tid] = (R0 + tid < N) ? g_scores[R0 + tid] : 0.0f;
        __syncthreads();
        if (tid < 128) {
            float q = 0.0f;
            #pragma unroll 8
            for (int d = 0; d < D; d++) q += xs[tid * PAD + d] * v1_s[d];
            q_s[tid] = q;
        }
        int nxt = ch + stride;
        if (nxt < nChunks) {
            int R1 = nxt * 128;
            #pragma unroll
            for (int u = 0; u < 8; u++) {
                int idx = tid + u * 512;
                int r = idx >> 5, c4 = idx & 31;
                int gr = R1 + r;
                pf[u] = (gr < N) ? ((const float4*)x)[(size_t)gr * 32 + c4]
                                 : make_float4(0.f, 0.f, 0.f, 0.f);
            }
        }
        __syncthreads();

        // GEMM1: z = x @ W1 (single-pass tf32)
        float cfr[2][4][4];
        #pragma unroll
        for (int mi = 0; mi < 2; mi++)
            #pragma unroll
            for (int ni = 0; ni < 4; ni++)
                #pragma unroll
                for (int j = 0; j < 4; j++) cfr[mi][ni][j] = 0.0f;

        #pragma unroll 2
        for (int ks = 0; ks < 16; ks++) {
            int k0 = ks * 8;
            uint32_t ah[2][4];
            #pragma unroll
            for (int mi = 0; mi < 2; mi++) {
                int r = wm * 32 + mi * 16 + gid;
                ah[mi][0] = tf32cvt(xs[r * PAD + k0 + tg]);
                ah[mi][1] = tf32cvt(xs[(r + 8) * PAD + k0 + tg]);
                ah[mi][2] = tf32cvt(xs[r * PAD + k0 + tg + 4]);
                ah[mi][3] = tf32cvt(xs[(r + 8) * PAD + k0 + tg + 4]);
            }
            uint32_t bh[4][2];
            #pragma unroll
            for (int ni = 0; ni < 4; ni++) {
                int c = wn * 32 + ni * 8 + gid;
                bh[ni][0] = __float_as_uint(w1t[c * PAD + k0 + tg]);
                bh[ni][1] = __float_as_uint(w1t[c * PAD + k0 + tg + 4]);
            }
            #pragma unroll
            for (int mi = 0; mi < 2; mi++)
                #pragma unroll
                for (int ni = 0; ni < 4; ni++)
                    mma_tf32(cfr[mi][ni], ah[mi][0], ah[mi][1], ah[mi][2], ah[mi][3], bh[ni][0], bh[ni][1]);
        }
        __syncthreads();

        // epilogue1: save residual x (thread-local read-before-write), relu, store PRE-ROUNDED tf32
        float xv_keep[2][4][4];
        #pragma unroll
        for (int mi = 0; mi < 2; mi++) {
            int r = wm * 32 + mi * 16 + gid;
            float qh0 = 0.5f * q_s[r], qh8 = 0.5f * q_s[r + 8];
            #pragma unroll
            for (int ni = 0; ni < 4; ni++) {
                int c = wn * 32 + ni * 8 + 2 * tg;
                float2 xo0 = *(const float2*)&xs[r * PAD + c];
                float2 xo1 = *(const float2*)&xs[(r + 8) * PAD + c];
                xv_keep[mi][ni][0] = xo0.x; xv_keep[mi][ni][1] = xo0.y;
                xv_keep[mi][ni][2] = xo1.x; xv_keep[mi][ni][3] = xo1.y;
                float z00 = 0.5f * cfr[mi][ni][0] + qh0 * a1_s[c]     + be1_s[c];
                float z01 = 0.5f * cfr[mi][ni][1] + qh0 * a1_s[c + 1] + be1_s[c + 1];
                float z10 = 0.5f * cfr[mi][ni][2] + qh8 * a1_s[c]     + be1_s[c];
                float z11 = 0.5f * cfr[mi][ni][3] + qh8 * a1_s[c + 1] + be1_s[c + 1];
                float2 p0 = make_float2(__uint_as_float(tf32cvt(fmaxf(z00, 0.f))),
                                        __uint_as_float(tf32cvt(fmaxf(z01, 0.f))));
                float2 p1 = make_float2(__uint_as_float(tf32cvt(fmaxf(z10, 0.f))),
                                        __uint_as_float(tf32cvt(fmaxf(z11, 0.f))));
                *(float2*)&xs[r * PAD + c]       = p0;
                *(float2*)&xs[(r + 8) * PAD + c] = p1;
            }
        }
        __syncthreads();

        // GEMM2: single pass, A pre-rounded
        #pragma unroll
        for (int mi = 0; mi < 2; mi++)
            #pragma unroll
            for (int ni = 0; ni < 4; ni++)
                #pragma unroll
                for (int j = 0; j < 4; j++) cfr[mi][ni][j] = 0.0f;

        #pragma unroll 2
        for (int ks = 0; ks < 16; ks++) {
            int k0 = ks * 8;
            uint32_t a2[2][4];
            #pragma unroll
            for (int mi = 0; mi < 2; mi++) {
                int r = wm * 32 + mi * 16 + gid;
                a2[mi][0] = __float_as_uint(xs[r * PAD + k0 + tg]);
                a2[mi][1] = __float_as_uint(xs[(r + 8) * PAD + k0 + tg]);
                a2[mi][2] = __float_as_uint(xs[r * PAD + k0 + tg + 4]);
                a2[mi][3] = __float_as_uint(xs[(r + 8) * PAD + k0 + tg + 4]);
            }
            uint32_t bh[4][2];
            #pragma unroll
            for (int ni = 0; ni < 4; ni++) {
                int c = wn * 32 + ni * 8 + gid;
                bh[ni][0] = __float_as_uint(w2t[c * PAD + k0 + tg]);
                bh[ni][1] = __float_as_uint(w2t[c * PAD + k0 + tg + 4]);
            }
            #pragma unroll
            for (int mi = 0; mi < 2; mi++)
                #pragma unroll
                for (int ni = 0; ni < 4; ni++)
                    mma_tf32(cfr[mi][ni], a2[mi][0], a2[mi][1], a2[mi][2], a2[mi][3], bh[ni][0], bh[ni][1]);
        }

        // epilogue2: residual from registers (no x re-read)
        #pragma unroll
        for (int mi = 0; mi < 2; mi++) {
            int r = wm * 32 + mi * 16 + gid;
            #pragma unroll
            for (int rr = 0; rr < 2; rr++) {
                int row = r + rr * 8;
                int gr = R0 + row;
                if (gr >= N) continue;
                float sc = sc_s[row], qh = 0.5f * q_s[row];
                #pragma unroll
                for (int ni = 0; ni < 4; ni++) {
                    int c = wn * 32 + ni * 8 + 2 * tg;
                    float e0 = cfr[mi][ni][rr * 2 + 0];
                    float e1 = cfr[mi][ni][rr * 2 + 1];
                    float o0 = (e0 + be2_s[c])     * sc + 0.5f * xv_keep[mi][ni][rr * 2 + 0] + qh * v1_s[c];
                    float o1 = (e1 + be2_s[c + 1]) * sc + 0.5f * xv_keep[mi][ni][rr * 2 + 1] + qh * v1_s[c + 1];
                    ((float2*)out)[(size_t)gr * 64 + (c >> 1)] = make_float2(o0, o1);
                }
            }
        }
    }
}

// ---------------------------------------------------------------- launch
extern "C" void kernel_launch(void* const* d_in, const int* in_sizes, int n_in,
                              void* d_out, int out_size) {
    const float* x       = (const float*)d_in[0];
    const void*  ei      = d_in[1];
    const float* ew      = (const float*)d_in[2];
    const float* w_gcn   = (const float*)d_in[3];
    const float* b_gcn   = (const float*)d_in[4];
    const float* w_score = (const float*)d_in[5];
    const float* b_score = (const float*)d_in[6];
    const float* alpha   = (const float*)d_in[7];
    const float* beta    = (const float*)d_in[8];
    const float* w_e1    = (const float*)d_in[9];
    const float* b_e1    = (const float*)d_in[10];
    const float* w_e2    = (const float*)d_in[11];
    const float* b_e2    = (const float*)d_in[12];
    float* out = (float*)d_out;

    int N = in_sizes[0] / D;
    int E = in_sizes[2];
    int nChunks = (N + 127) / 128;
    int NB = (N + 255) / 256;
    int E2 = (E + 1) / 2;
    int EB2 = (E2 + 255) / 256;
    int ZB = (N + 255) / 256;
    int PB = (N * 32 + 255) / 256;

    const int SMG = 2 * 128 * PADG * 4;
    const int SMF = (3 * 128 * PAD + 256) * 4;
    const int SMP = (128 * PAD) * 4;

    static int init_done = 0;
    static cudaStream_t s1, s2;
    static cudaEvent_t evFork, evScores, evGate, evPre, evP, evZ;
    if (!init_done) {
        cudaFuncSetAttribute(k_G,      cudaFuncAttributeMaxDynamicSharedMemorySize, SMG);
        cudaFuncSetAttribute(k_power,  cudaFuncAttributeMaxDynamicSharedMemorySize, SMP);
        cudaFuncSetAttribute(k_final3, cudaFuncAttributeMaxDynamicSharedMemorySize, SMF);
        cudaStreamCreateWithFlags(&s1, cudaStreamNonBlocking);
        cudaStreamCreateWithFlags(&s2, cudaStreamNonBlocking);
        cudaEventCreateWithFlags(&evFork,   cudaEventDisableTiming);
        cudaEventCreateWithFlags(&evScores, cudaEventDisableTiming);
        cudaEventCreateWithFlags(&evGate,   cudaEventDisableTiming);
        cudaEventCreateWithFlags(&evPre,    cudaEventDisableTiming);
        cudaEventCreateWithFlags(&evP,      cudaEventDisableTiming);
        cudaEventCreateWithFlags(&evZ,      cudaEventDisableTiming);
        init_done = 1;
    }

    // s0 first: zero everything (degi + G + bar), publish evZ
    k_zeroAll<<<ZB, 256>>>(N);
    cudaEventRecord(evZ, 0);

    cudaEventRecord(evFork, 0);
    cudaStreamWaitEvent(s1, evFork, 0);

    // s1: tiny prologue (detect + wv), then edge chain
    k_pre3<<<2, 256, 0, s1>>>((const long long*)ei, E, N, w_gcn, b_gcn, w_score, b_score);
    cudaEventRecord(evPre, s1);
    cudaStreamWaitEvent(s2, evPre, 0);
    k_p<<<PB, 256, 0, s2>>>(x, N);            // needs wv; concurrent with k_deg
    cudaEventRecord(evP, s2);

    k_deg<<<EB2, 256, 0, s1>>>(ei, E);        // degi zeroed via evFork (recorded after k_zeroAll)
    cudaStreamWaitEvent(s1, evP, 0);          // dinv needs p + deg
    k_dinv<<<NB, 256, 0, s1>>>(N);
    k_edge<<<EB2, 256, 0, s1>>>(ei, E);
    k_scores<<<NB, 256, 0, s1>>>(N);
    cudaEventRecord(evScores, s1);
    k_gate<<<EB2, 256, 0, s1>>>(ei, ew, alpha, beta, out + (size_t)N * D, E);   // overlaps k_final3
    cudaEventRecord(evGate, s1);

    // s0 critical path
    k_G<<<148, 512, SMG>>>(x, N, nChunks);
    k_power<<<PWB, 1024, SMP>>>(w_e1);

    cudaStreamWaitEvent(0, evScores, 0);
    k_final3<<<148, 512, SMF>>>(x, b_e1, b_e2, w_e1, w_e2, out, N, nChunks);
    cudaStreamWaitEvent(0, evGate, 0);   // join s1 fully for capture
}